// round 1
// baseline (speedup 1.0000x reference)
#include <cuda_runtime.h>
#include <math.h>
#include <stdint.h>

#define D_MODEL 1024
#define NSEQ    4096
#define HEADS   16
#define DH      64

// Scratch (allocation-free rule: __device__ globals)
__device__ float g_q[NSEQ * D_MODEL];
__device__ float g_k[NSEQ * D_MODEL];
__device__ float g_v[NSEQ * D_MODEL];
__device__ float g_o[NSEQ * D_MODEL];

// ---------------------------------------------------------------------------
// SGEMM: C[M,N] = A[M,K] @ B[K,N], row-major, all dims multiples of tile sizes
// ---------------------------------------------------------------------------
#define BM 128
#define BN 128
#define BK 16

__global__ __launch_bounds__(256) void sgemm_kernel(
    const float* __restrict__ A, const float* __restrict__ B,
    float* __restrict__ C, int M, int N, int K)
{
    __shared__ float As[BK][BM];
    __shared__ float Bs[BK][BN];

    const int row0 = blockIdx.y * BM;
    const int col0 = blockIdx.x * BN;
    const int t  = threadIdx.x;
    const int tx = t & 15;   // 0..15
    const int ty = t >> 4;   // 0..15

    float acc[8][8];
    #pragma unroll
    for (int i = 0; i < 8; i++)
        #pragma unroll
        for (int j = 0; j < 8; j++) acc[i][j] = 0.f;

    for (int k0 = 0; k0 < K; k0 += BK) {
        // Load A tile (BM x BK) -> As[BK][BM] transposed. 512 float4 total.
        #pragma unroll
        for (int l = 0; l < 2; l++) {
            int id = t + l * 256;
            int r  = id >> 2;     // 0..127
            int kq = id & 3;      // 0..3
            float4 a = *(const float4*)(A + (size_t)(row0 + r) * K + k0 + kq * 4);
            As[kq * 4 + 0][r] = a.x;
            As[kq * 4 + 1][r] = a.y;
            As[kq * 4 + 2][r] = a.z;
            As[kq * 4 + 3][r] = a.w;
        }
        // Load B tile (BK x BN) directly. 512 float4 total.
        #pragma unroll
        for (int l = 0; l < 2; l++) {
            int id = t + l * 256;
            int r  = id >> 5;     // 0..15
            int c4 = id & 31;     // 0..31
            *(float4*)(&Bs[r][c4 * 4]) =
                *(const float4*)(B + (size_t)(k0 + r) * N + col0 + c4 * 4);
        }
        __syncthreads();

        #pragma unroll
        for (int kk = 0; kk < BK; kk++) {
            float a[8], b[8];
            *(float4*)(a)     = *(float4*)(&As[kk][ty * 8]);
            *(float4*)(a + 4) = *(float4*)(&As[kk][ty * 8 + 4]);
            *(float4*)(b)     = *(float4*)(&Bs[kk][tx * 8]);
            *(float4*)(b + 4) = *(float4*)(&Bs[kk][tx * 8 + 4]);
            #pragma unroll
            for (int i = 0; i < 8; i++)
                #pragma unroll
                for (int j = 0; j < 8; j++)
                    acc[i][j] = fmaf(a[i], b[j], acc[i][j]);
        }
        __syncthreads();
    }

    #pragma unroll
    for (int i = 0; i < 8; i++) {
        float* cp = C + (size_t)(row0 + ty * 8 + i) * N + col0 + tx * 8;
        *(float4*)(cp)     = make_float4(acc[i][0], acc[i][1], acc[i][2], acc[i][3]);
        *(float4*)(cp + 4) = make_float4(acc[i][4], acc[i][5], acc[i][6], acc[i][7]);
    }
}

// ---------------------------------------------------------------------------
// L2 normalize 64-element head rows: t / max(||t||, 1e-12). One warp per row.
// Layout: buf is [n, h*dh] contiguous, so row w starts at w*64.
// ---------------------------------------------------------------------------
__global__ void l2norm_kernel(float* __restrict__ buf, int rows)
{
    int w    = (blockIdx.x * blockDim.x + threadIdx.x) >> 5;
    int lane = threadIdx.x & 31;
    if (w >= rows) return;
    float* p = buf + (size_t)w * DH;
    float v0 = p[lane];
    float v1 = p[lane + 32];
    float ss = v0 * v0 + v1 * v1;
    #pragma unroll
    for (int off = 16; off; off >>= 1)
        ss += __shfl_xor_sync(0xffffffffu, ss, off);
    float nrm = sqrtf(ss);
    float s = 1.0f / fmaxf(nrm, 1e-12f);
    p[lane]      = v0 * s;
    p[lane + 32] = v1 * s;
}

// ---------------------------------------------------------------------------
// Flash-attention (causal, cosine-sim scale=8). BM=BN=64, DH=64, 256 threads.
// grid = (qblocks, heads). Online softmax, stats replicated across the
// 16-thread row group (shfl.bfly reductions).
// ---------------------------------------------------------------------------
#define FPAD 65
#define FSMEM (4 * 64 * FPAD * 4)

__global__ __launch_bounds__(256) void flash_kernel(
    const float* __restrict__ q, const float* __restrict__ k,
    const float* __restrict__ v, float* __restrict__ o)
{
    extern __shared__ float sm[];
    float* Qs = sm;                 // 64 x FPAD
    float* Ks = Qs + 64 * FPAD;
    float* Vs = Ks + 64 * FPAD;
    float* Ps = Vs + 64 * FPAD;

    const int qb   = blockIdx.x;
    const int head = blockIdx.y;
    const int t  = threadIdx.x;
    const int tx = t & 15;
    const int ty = t >> 4;
    const int i0 = ty * 4;   // query rows owned
    const int j0 = tx * 4;   // key cols / dh cols owned
    const size_t hoff = (size_t)head * DH;

    // Load Q tile once
    #pragma unroll
    for (int l = 0; l < 16; l++) {
        int idx = t + l * 256;
        int r = idx >> 6, c = idx & 63;
        Qs[r * FPAD + c] = q[(size_t)(qb * 64 + r) * D_MODEL + hoff + c];
    }

    float m[4], lsum[4], acc[4][4];
    #pragma unroll
    for (int ii = 0; ii < 4; ii++) {
        m[ii] = -1e30f; lsum[ii] = 0.f;
        #pragma unroll
        for (int jj = 0; jj < 4; jj++) acc[ii][jj] = 0.f;
    }

    for (int jb = 0; jb <= qb; jb++) {
        __syncthreads();   // protect Ks/Vs/Ps from previous iteration
        #pragma unroll
        for (int l = 0; l < 16; l++) {
            int idx = t + l * 256;
            int r = idx >> 6, c = idx & 63;
            Ks[r * FPAD + c] = k[(size_t)(jb * 64 + r) * D_MODEL + hoff + c];
            Vs[r * FPAD + c] = v[(size_t)(jb * 64 + r) * D_MODEL + hoff + c];
        }
        __syncthreads();

        // S = (Q . K^T) * 8  (4x4 per thread)
        float s[4][4];
        #pragma unroll
        for (int ii = 0; ii < 4; ii++)
            #pragma unroll
            for (int jj = 0; jj < 4; jj++) s[ii][jj] = 0.f;

        #pragma unroll 4
        for (int kk = 0; kk < 64; kk++) {
            float qf[4], kf[4];
            #pragma unroll
            for (int ii = 0; ii < 4; ii++) qf[ii] = Qs[(i0 + ii) * FPAD + kk];
            #pragma unroll
            for (int jj = 0; jj < 4; jj++) kf[jj] = Ks[(j0 + jj) * FPAD + kk];
            #pragma unroll
            for (int ii = 0; ii < 4; ii++)
                #pragma unroll
                for (int jj = 0; jj < 4; jj++)
                    s[ii][jj] = fmaf(qf[ii], kf[jj], s[ii][jj]);
        }

        // scale + causal mask (diagonal tile only)
        #pragma unroll
        for (int ii = 0; ii < 4; ii++)
            #pragma unroll
            for (int jj = 0; jj < 4; jj++) {
                s[ii][jj] *= 8.0f;
                if (jb == qb && (j0 + jj) > (i0 + ii)) s[ii][jj] = -1e30f;
            }

        // online softmax update (row stats replicated via 16-lane shfl)
        #pragma unroll
        for (int ii = 0; ii < 4; ii++) {
            float mx = fmaxf(fmaxf(s[ii][0], s[ii][1]), fmaxf(s[ii][2], s[ii][3]));
            #pragma unroll
            for (int off = 8; off; off >>= 1)
                mx = fmaxf(mx, __shfl_xor_sync(0xffffffffu, mx, off));
            float mn   = fmaxf(m[ii], mx);
            float corr = __expf(m[ii] - mn);
            m[ii] = mn;
            float rs = 0.f;
            #pragma unroll
            for (int jj = 0; jj < 4; jj++) {
                float p = __expf(s[ii][jj] - mn);
                s[ii][jj] = p;
                rs += p;
            }
            #pragma unroll
            for (int off = 8; off; off >>= 1)
                rs += __shfl_xor_sync(0xffffffffu, rs, off);
            lsum[ii] = lsum[ii] * corr + rs;
            #pragma unroll
            for (int jj = 0; jj < 4; jj++) acc[ii][jj] *= corr;
        }

        // stage P to smem for the PV GEMM
        #pragma unroll
        for (int ii = 0; ii < 4; ii++)
            #pragma unroll
            for (int jj = 0; jj < 4; jj++)
                Ps[(i0 + ii) * FPAD + j0 + jj] = s[ii][jj];
        __syncthreads();

        // O += P @ V  (thread owns rows i0..i0+3, dh cols j0..j0+3)
        #pragma unroll 4
        for (int j = 0; j < 64; j++) {
            float vf[4], pf[4];
            #pragma unroll
            for (int jj = 0; jj < 4; jj++) vf[jj] = Vs[j * FPAD + j0 + jj];
            #pragma unroll
            for (int ii = 0; ii < 4; ii++) pf[ii] = Ps[(i0 + ii) * FPAD + j];
            #pragma unroll
            for (int ii = 0; ii < 4; ii++)
                #pragma unroll
                for (int jj = 0; jj < 4; jj++)
                    acc[ii][jj] = fmaf(pf[ii], vf[jj], acc[ii][jj]);
        }
    }

    #pragma unroll
    for (int ii = 0; ii < 4; ii++) {
        float inv = 1.0f / lsum[ii];
        #pragma unroll
        for (int jj = 0; jj < 4; jj++)
            o[(size_t)(qb * 64 + i0 + ii) * D_MODEL + hoff + j0 + jj] =
                acc[ii][jj] * inv;
    }
}

// ---------------------------------------------------------------------------
extern "C" void kernel_launch(void* const* d_in, const int* in_sizes, int n_in,
                              void* d_out, int out_size)
{
    const float* x  = (const float*)d_in[0];
    const float* Wq = (const float*)d_in[1];
    const float* Wk = (const float*)d_in[2];
    const float* Wv = (const float*)d_in[3];
    const float* Wo = (const float*)d_in[4];

    float *q, *k, *v, *o;
    cudaGetSymbolAddress((void**)&q, g_q);
    cudaGetSymbolAddress((void**)&k, g_k);
    cudaGetSymbolAddress((void**)&v, g_v);
    cudaGetSymbolAddress((void**)&o, g_o);

    dim3 ggrid(D_MODEL / BN, NSEQ / BM);   // (8, 32)

    sgemm_kernel<<<ggrid, 256>>>(x, Wq, q, NSEQ, D_MODEL, D_MODEL);
    sgemm_kernel<<<ggrid, 256>>>(x, Wk, k, NSEQ, D_MODEL, D_MODEL);
    sgemm_kernel<<<ggrid, 256>>>(x, Wv, v, NSEQ, D_MODEL, D_MODEL);

    int rows = NSEQ * HEADS;               // 65536 rows of 64
    l2norm_kernel<<<rows / 8, 256>>>(q, rows);
    l2norm_kernel<<<rows / 8, 256>>>(k, rows);

    cudaFuncSetAttribute(flash_kernel,
                         cudaFuncAttributeMaxDynamicSharedMemorySize, FSMEM);
    flash_kernel<<<dim3(NSEQ / 64, HEADS), 256, FSMEM>>>(q, k, v, o);

    sgemm_kernel<<<ggrid, 256>>>(o, Wo, (float*)d_out, NSEQ, D_MODEL, D_MODEL);
}

// round 3
// speedup vs baseline: 1.2387x; 1.2387x over previous
#include <cuda_runtime.h>
#include <cuda_bf16.h>
#include <math.h>
#include <stdint.h>

#define D_MODEL 1024
#define NSEQ    4096
#define HEADS   16
#define DH      64

// Scratch (allocation-free rule: __device__ globals)
__device__ float g_q[NSEQ * D_MODEL];
__device__ float g_k[NSEQ * D_MODEL];
__device__ float g_v[NSEQ * D_MODEL];
__device__ float g_o[NSEQ * D_MODEL];
__device__ __nv_bfloat16 g_xhi[NSEQ * D_MODEL];
__device__ __nv_bfloat16 g_xlo[NSEQ * D_MODEL];
__device__ __nv_bfloat16 g_ohi[NSEQ * D_MODEL];
__device__ __nv_bfloat16 g_olo[NSEQ * D_MODEL];
__device__ __nv_bfloat16 g_wh[D_MODEL * D_MODEL];   // W^T hi  [N][K]
__device__ __nv_bfloat16 g_wl[D_MODEL * D_MODEL];   // W^T lo  [N][K]

__device__ __forceinline__ uint32_t smem_u32(const void* p) {
    uint32_t a;
    asm("{ .reg .u64 t; cvta.to.shared.u64 t, %1; cvt.u32.u64 %0, t; }"
        : "=r"(a) : "l"(p));
    return a;
}

// ---------------------------------------------------------------------------
// split: fp32 -> (hi, lo) bf16, same layout. 4 elements / thread.
// ---------------------------------------------------------------------------
__global__ void split_kernel(const float* __restrict__ in,
                             __nv_bfloat16* __restrict__ hi,
                             __nv_bfloat16* __restrict__ lo)
{
    int i = blockIdx.x * blockDim.x + threadIdx.x;
    float4 v = ((const float4*)in)[i];
    __nv_bfloat16 h0 = __float2bfloat16(v.x), h1 = __float2bfloat16(v.y);
    __nv_bfloat16 h2 = __float2bfloat16(v.z), h3 = __float2bfloat16(v.w);
    __nv_bfloat16 l0 = __float2bfloat16(v.x - __bfloat162float(h0));
    __nv_bfloat16 l1 = __float2bfloat16(v.y - __bfloat162float(h1));
    __nv_bfloat16 l2 = __float2bfloat16(v.z - __bfloat162float(h2));
    __nv_bfloat16 l3 = __float2bfloat16(v.w - __bfloat162float(h3));
    __nv_bfloat162 hA = __halves2bfloat162(h0, h1), hB = __halves2bfloat162(h2, h3);
    __nv_bfloat162 lA = __halves2bfloat162(l0, l1), lB = __halves2bfloat162(l2, l3);
    ((uint2*)hi)[i] = make_uint2(*(uint32_t*)&hA, *(uint32_t*)&hB);
    ((uint2*)lo)[i] = make_uint2(*(uint32_t*)&lA, *(uint32_t*)&lB);
}

// ---------------------------------------------------------------------------
// transpose-convert: W[k][n] fp32 -> W^T hi/lo bf16 [n][k].  32x32 tiles.
// ---------------------------------------------------------------------------
__global__ void tconv_kernel(const float* __restrict__ W,
                             __nv_bfloat16* __restrict__ hiT,
                             __nv_bfloat16* __restrict__ loT)
{
    __shared__ float tile[32][33];
    const int n0 = blockIdx.x * 32, k0 = blockIdx.y * 32;
    const int tx = threadIdx.x, ty = threadIdx.y;   // 32 x 8
    #pragma unroll
    for (int j = 0; j < 4; j++)
        tile[ty + 8 * j][tx] = W[(size_t)(k0 + ty + 8 * j) * D_MODEL + n0 + tx];
    __syncthreads();
    #pragma unroll
    for (int j = 0; j < 4; j++) {
        float v = tile[tx][ty + 8 * j];
        __nv_bfloat16 h = __float2bfloat16(v);
        __nv_bfloat16 l = __float2bfloat16(v - __bfloat162float(h));
        size_t o = (size_t)(n0 + ty + 8 * j) * D_MODEL + k0 + tx;
        hiT[o] = h;
        loT[o] = l;
    }
}

// ---------------------------------------------------------------------------
// GEMM via mma.sync m16n8k16 bf16 with hi/lo split (3 MMAs per product).
// C[M,N] = A[M,K] @ B[K,N].  A given as (Ahi,Alo) [M][K]; B as transposed
// (BhiT,BloT) [N][K].  CTA: 64x64 tile, 128 threads (4 warps, 2x2), BK=32.
// ---------------------------------------------------------------------------
#define GSTR 40   // smem row stride in halves (64x40)

__device__ __forceinline__ void ldm4(uint32_t r[4], uint32_t addr) {
    asm volatile("ldmatrix.sync.aligned.m8n8.x4.shared.b16 {%0,%1,%2,%3}, [%4];"
                 : "=r"(r[0]), "=r"(r[1]), "=r"(r[2]), "=r"(r[3]) : "r"(addr));
}

__device__ __forceinline__ void mma16816(float d[4], const uint32_t a[4],
                                         uint32_t b0, uint32_t b1) {
    asm volatile(
        "mma.sync.aligned.m16n8k16.row.col.f32.bf16.bf16.f32 "
        "{%0,%1,%2,%3}, {%4,%5,%6,%7}, {%8,%9}, {%0,%1,%2,%3};"
        : "+f"(d[0]), "+f"(d[1]), "+f"(d[2]), "+f"(d[3])
        : "r"(a[0]), "r"(a[1]), "r"(a[2]), "r"(a[3]), "r"(b0), "r"(b1));
}

__global__ __launch_bounds__(128, 3) void gemm_bs(
    const __nv_bfloat16* __restrict__ Ahi, const __nv_bfloat16* __restrict__ Alo,
    const __nv_bfloat16* __restrict__ BhiT, const __nv_bfloat16* __restrict__ BloT,
    float* __restrict__ C, int M, int N, int K)
{
    __shared__ __align__(16) __nv_bfloat16 sAh[64][GSTR], sAl[64][GSTR];
    __shared__ __align__(16) __nv_bfloat16 sBh[64][GSTR], sBl[64][GSTR];

    const int t = threadIdx.x;
    const int wid = t >> 5, lane = t & 31;
    const int row0 = blockIdx.y * 64, col0 = blockIdx.x * 64;
    const int wm = (wid >> 1) * 32;   // warp row offset
    const int wn = (wid & 1) * 32;    // warp col offset

    float acc[2][4][4];
    #pragma unroll
    for (int i = 0; i < 2; i++)
        #pragma unroll
        for (int j = 0; j < 4; j++)
            #pragma unroll
            for (int q = 0; q < 4; q++) acc[i][j][q] = 0.f;

    // prefetch regs: 2 uint4 per matrix (A hi/lo, B hi/lo)
    uint4 pah[2], pal[2], pbh[2], pbl[2];
    {
        #pragma unroll
        for (int i = 0; i < 2; i++) {
            int id = t + i * 128, r = id >> 2, q = id & 3;
            size_t ao = (size_t)(row0 + r) * K + q * 8;
            size_t bo = (size_t)(col0 + r) * K + q * 8;
            pah[i] = *(const uint4*)(Ahi + ao);
            pal[i] = *(const uint4*)(Alo + ao);
            pbh[i] = *(const uint4*)(BhiT + bo);
            pbl[i] = *(const uint4*)(BloT + bo);
        }
    }

    // precomputed ldmatrix smem addresses (depend only on lane)
    const int a_row = (lane & 7) + (lane & 8);
    const int a_col = (lane >> 4) << 3;
    const int b_row = (lane & 7) + ((lane & 16) >> 1);
    const int b_col = lane & 8;

    const int NCH = K >> 5;   // 32
    for (int c = 0; c < NCH; c++) {
        __syncthreads();
        #pragma unroll
        for (int i = 0; i < 2; i++) {
            int id = t + i * 128, r = id >> 2, q = id & 3;
            *(uint4*)&sAh[r][q * 8] = pah[i];
            *(uint4*)&sAl[r][q * 8] = pal[i];
            *(uint4*)&sBh[r][q * 8] = pbh[i];
            *(uint4*)&sBl[r][q * 8] = pbl[i];
        }
        __syncthreads();

        if (c + 1 < NCH) {
            int k0 = (c + 1) * 32;
            #pragma unroll
            for (int i = 0; i < 2; i++) {
                int id = t + i * 128, r = id >> 2, q = id & 3;
                size_t ao = (size_t)(row0 + r) * K + k0 + q * 8;
                size_t bo = (size_t)(col0 + r) * K + k0 + q * 8;
                pah[i] = *(const uint4*)(Ahi + ao);
                pal[i] = *(const uint4*)(Alo + ao);
                pbh[i] = *(const uint4*)(BhiT + bo);
                pbl[i] = *(const uint4*)(BloT + bo);
            }
        }

        #pragma unroll
        for (int ks = 0; ks < 2; ks++) {
            const int kb = ks * 16;
            uint32_t ah[2][4], al[2][4], bh[2][4], bl[2][4];
            #pragma unroll
            for (int mt = 0; mt < 2; mt++) {
                int r = wm + mt * 16 + a_row, cc = kb + a_col;
                ldm4(ah[mt], smem_u32(&sAh[r][cc]));
                ldm4(al[mt], smem_u32(&sAl[r][cc]));
            }
            #pragma unroll
            for (int p = 0; p < 2; p++) {
                int r = wn + p * 16 + b_row, cc = kb + b_col;
                ldm4(bh[p], smem_u32(&sBh[r][cc]));
                ldm4(bl[p], smem_u32(&sBl[r][cc]));
            }
            #pragma unroll
            for (int mt = 0; mt < 2; mt++)
                #pragma unroll
                for (int nt = 0; nt < 4; nt++) {
                    int p = nt >> 1, s = (nt & 1) * 2;
                    mma16816(acc[mt][nt], ah[mt], bh[p][s], bh[p][s + 1]);
                    mma16816(acc[mt][nt], ah[mt], bl[p][s], bl[p][s + 1]);
                    mma16816(acc[mt][nt], al[mt], bh[p][s], bh[p][s + 1]);
                }
        }
    }

    // epilogue
    #pragma unroll
    for (int mt = 0; mt < 2; mt++)
        #pragma unroll
        for (int nt = 0; nt < 4; nt++) {
            int row = row0 + wm + mt * 16 + (lane >> 2);
            int col = col0 + wn + nt * 8 + (lane & 3) * 2;
            *(float2*)(C + (size_t)row * N + col) =
                make_float2(acc[mt][nt][0], acc[mt][nt][1]);
            *(float2*)(C + (size_t)(row + 8) * N + col) =
                make_float2(acc[mt][nt][2], acc[mt][nt][3]);
        }
}

// ---------------------------------------------------------------------------
// L2 normalize 64-element head rows. One warp per row.
// ---------------------------------------------------------------------------
__global__ void l2norm_kernel(float* __restrict__ buf, int rows)
{
    int w    = (blockIdx.x * blockDim.x + threadIdx.x) >> 5;
    int lane = threadIdx.x & 31;
    if (w >= rows) return;
    float* p = buf + (size_t)w * DH;
    float v0 = p[lane];
    float v1 = p[lane + 32];
    float ss = v0 * v0 + v1 * v1;
    #pragma unroll
    for (int off = 16; off; off >>= 1)
        ss += __shfl_xor_sync(0xffffffffu, ss, off);
    float nrm = sqrtf(ss);
    float s = 1.0f / fmaxf(nrm, 1e-12f);
    p[lane]      = v0 * s;
    p[lane + 32] = v1 * s;
}

// ---------------------------------------------------------------------------
// Flash-attention (causal, cosine-sim scale=8). BM=BN=64, DH=64, 256 threads.
// ---------------------------------------------------------------------------
#define FPAD 65
#define FSMEM (4 * 64 * FPAD * 4)

__global__ __launch_bounds__(256) void flash_kernel(
    const float* __restrict__ q, const float* __restrict__ k,
    const float* __restrict__ v, float* __restrict__ o)
{
    extern __shared__ float smf[];
    float* Qs = smf;
    float* Ks = Qs + 64 * FPAD;
    float* Vs = Ks + 64 * FPAD;
    float* Ps = Vs + 64 * FPAD;

    const int qb   = blockIdx.x;
    const int head = blockIdx.y;
    const int t  = threadIdx.x;
    const int tx = t & 15;
    const int ty = t >> 4;
    const int i0 = ty * 4;
    const int j0 = tx * 4;
    const size_t hoff = (size_t)head * DH;

    #pragma unroll
    for (int l = 0; l < 16; l++) {
        int idx = t + l * 256;
        int r = idx >> 6, c = idx & 63;
        Qs[r * FPAD + c] = q[(size_t)(qb * 64 + r) * D_MODEL + hoff + c];
    }

    float m[4], lsum[4], acc[4][4];
    #pragma unroll
    for (int ii = 0; ii < 4; ii++) {
        m[ii] = -1e30f; lsum[ii] = 0.f;
        #pragma unroll
        for (int jj = 0; jj < 4; jj++) acc[ii][jj] = 0.f;
    }

    for (int jb = 0; jb <= qb; jb++) {
        __syncthreads();
        #pragma unroll
        for (int l = 0; l < 16; l++) {
            int idx = t + l * 256;
            int r = idx >> 6, c = idx & 63;
            Ks[r * FPAD + c] = k[(size_t)(jb * 64 + r) * D_MODEL + hoff + c];
            Vs[r * FPAD + c] = v[(size_t)(jb * 64 + r) * D_MODEL + hoff + c];
        }
        __syncthreads();

        float s[4][4];
        #pragma unroll
        for (int ii = 0; ii < 4; ii++)
            #pragma unroll
            for (int jj = 0; jj < 4; jj++) s[ii][jj] = 0.f;

        #pragma unroll 4
        for (int kk = 0; kk < 64; kk++) {
            float qf[4], kf[4];
            #pragma unroll
            for (int ii = 0; ii < 4; ii++) qf[ii] = Qs[(i0 + ii) * FPAD + kk];
            #pragma unroll
            for (int jj = 0; jj < 4; jj++) kf[jj] = Ks[(j0 + jj) * FPAD + kk];
            #pragma unroll
            for (int ii = 0; ii < 4; ii++)
                #pragma unroll
                for (int jj = 0; jj < 4; jj++)
                    s[ii][jj] = fmaf(qf[ii], kf[jj], s[ii][jj]);
        }

        #pragma unroll
        for (int ii = 0; ii < 4; ii++)
            #pragma unroll
            for (int jj = 0; jj < 4; jj++) {
                s[ii][jj] *= 8.0f;
                if (jb == qb && (j0 + jj) > (i0 + ii)) s[ii][jj] = -1e30f;
            }

        #pragma unroll
        for (int ii = 0; ii < 4; ii++) {
            float mx = fmaxf(fmaxf(s[ii][0], s[ii][1]), fmaxf(s[ii][2], s[ii][3]));
            #pragma unroll
            for (int off = 8; off; off >>= 1)
                mx = fmaxf(mx, __shfl_xor_sync(0xffffffffu, mx, off));
            float mn   = fmaxf(m[ii], mx);
            float corr = __expf(m[ii] - mn);
            m[ii] = mn;
            float rs = 0.f;
            #pragma unroll
            for (int jj = 0; jj < 4; jj++) {
                float p = __expf(s[ii][jj] - mn);
                s[ii][jj] = p;
                rs += p;
            }
            #pragma unroll
            for (int off = 8; off; off >>= 1)
                rs += __shfl_xor_sync(0xffffffffu, rs, off);
            lsum[ii] = lsum[ii] * corr + rs;
            #pragma unroll
            for (int jj = 0; jj < 4; jj++) acc[ii][jj] *= corr;
        }

        #pragma unroll
        for (int ii = 0; ii < 4; ii++)
            #pragma unroll
            for (int jj = 0; jj < 4; jj++)
                Ps[(i0 + ii) * FPAD + j0 + jj] = s[ii][jj];
        __syncthreads();

        #pragma unroll 4
        for (int j = 0; j < 64; j++) {
            float vf[4], pf[4];
            #pragma unroll
            for (int jj = 0; jj < 4; jj++) vf[jj] = Vs[j * FPAD + j0 + jj];
            #pragma unroll
            for (int ii = 0; ii < 4; ii++) pf[ii] = Ps[(i0 + ii) * FPAD + j];
            #pragma unroll
            for (int ii = 0; ii < 4; ii++)
                #pragma unroll
                for (int jj = 0; jj < 4; jj++)
                    acc[ii][jj] = fmaf(pf[ii], vf[jj], acc[ii][jj]);
        }
    }

    #pragma unroll
    for (int ii = 0; ii < 4; ii++) {
        float inv = 1.0f / lsum[ii];
        #pragma unroll
        for (int jj = 0; jj < 4; jj++)
            o[(size_t)(qb * 64 + i0 + ii) * D_MODEL + hoff + j0 + jj] =
                acc[ii][jj] * inv;
    }
}

// ---------------------------------------------------------------------------
extern "C" void kernel_launch(void* const* d_in, const int* in_sizes, int n_in,
                              void* d_out, int out_size)
{
    const float* x  = (const float*)d_in[0];
    const float* Wq = (const float*)d_in[1];
    const float* Wk = (const float*)d_in[2];
    const float* Wv = (const float*)d_in[3];
    const float* Wo = (const float*)d_in[4];

    float *q, *k, *v, *o;
    __nv_bfloat16 *xhi, *xlo, *ohi, *olo, *wh, *wl;
    cudaGetSymbolAddress((void**)&q, g_q);
    cudaGetSymbolAddress((void**)&k, g_k);
    cudaGetSymbolAddress((void**)&v, g_v);
    cudaGetSymbolAddress((void**)&o, g_o);
    cudaGetSymbolAddress((void**)&xhi, g_xhi);
    cudaGetSymbolAddress((void**)&xlo, g_xlo);
    cudaGetSymbolAddress((void**)&ohi, g_ohi);
    cudaGetSymbolAddress((void**)&olo, g_olo);
    cudaGetSymbolAddress((void**)&wh, g_wh);
    cudaGetSymbolAddress((void**)&wl, g_wl);

    cudaFuncSetAttribute(flash_kernel,
                         cudaFuncAttributeMaxDynamicSharedMemorySize, FSMEM);

    const int NE4 = NSEQ * D_MODEL / 4;       // float4 count
    dim3 tgrid(D_MODEL / 32, D_MODEL / 32);
    dim3 tblk(32, 8);
    dim3 ggrid(D_MODEL / 64, NSEQ / 64);      // (16, 64)

    split_kernel<<<NE4 / 256, 256>>>(x, xhi, xlo);

    tconv_kernel<<<tgrid, tblk>>>(Wq, wh, wl);
    gemm_bs<<<ggrid, 128>>>(xhi, xlo, wh, wl, q, NSEQ, D_MODEL, D_MODEL);
    tconv_kernel<<<tgrid, tblk>>>(Wk, wh, wl);
    gemm_bs<<<ggrid, 128>>>(xhi, xlo, wh, wl, k, NSEQ, D_MODEL, D_MODEL);
    tconv_kernel<<<tgrid, tblk>>>(Wv, wh, wl);
    gemm_bs<<<ggrid, 128>>>(xhi, xlo, wh, wl, v, NSEQ, D_MODEL, D_MODEL);

    int rows = NSEQ * HEADS;
    l2norm_kernel<<<rows / 8, 256>>>(q, rows);
    l2norm_kernel<<<rows / 8, 256>>>(k, rows);

    flash_kernel<<<dim3(NSEQ / 64, HEADS), 256, FSMEM>>>(q, k, v, o);

    split_kernel<<<NE4 / 256, 256>>>(o, ohi, olo);
    tconv_kernel<<<tgrid, tblk>>>(Wo, wh, wl);
    gemm_bs<<<ggrid, 128>>>(ohi, olo, wh, wl, (float*)d_out, NSEQ, D_MODEL, D_MODEL);
}

// round 5
// speedup vs baseline: 1.2708x; 1.0259x over previous
#include <cuda_runtime.h>
#include <cuda_bf16.h>
#include <math.h>
#include <stdint.h>

#define D_MODEL 1024
#define D3      3072
#define NSEQ    4096
#define HEADS   16
#define DH      64

// Scratch (allocation-free rule: __device__ globals)
__device__ float g_qkv[NSEQ * D3];                  // fused q|k|v, stride 3072
__device__ __nv_bfloat16 g_xhi[NSEQ * D_MODEL];
__device__ __nv_bfloat16 g_xlo[NSEQ * D_MODEL];
__device__ __nv_bfloat16 g_ohi[NSEQ * D_MODEL];
__device__ __nv_bfloat16 g_olo[NSEQ * D_MODEL];
__device__ __nv_bfloat16 g_wh[D3 * D_MODEL];        // W^T hi  [N][K] (concat)
__device__ __nv_bfloat16 g_wl[D3 * D_MODEL];        // W^T lo  [N][K]

__device__ __forceinline__ uint32_t smem_u32(const void* p) {
    uint32_t a;
    asm("{ .reg .u64 t; cvta.to.shared.u64 t, %1; cvt.u32.u64 %0, t; }"
        : "=r"(a) : "l"(p));
    return a;
}

// ---------------------------------------------------------------------------
// split: fp32 -> (hi, lo) bf16, same layout. 4 elements / thread.
// ---------------------------------------------------------------------------
__global__ void split_kernel(const float* __restrict__ in,
                             __nv_bfloat16* __restrict__ hi,
                             __nv_bfloat16* __restrict__ lo)
{
    int i = blockIdx.x * blockDim.x + threadIdx.x;
    float4 v = ((const float4*)in)[i];
    __nv_bfloat16 h0 = __float2bfloat16(v.x), h1 = __float2bfloat16(v.y);
    __nv_bfloat16 h2 = __float2bfloat16(v.z), h3 = __float2bfloat16(v.w);
    __nv_bfloat16 l0 = __float2bfloat16(v.x - __bfloat162float(h0));
    __nv_bfloat16 l1 = __float2bfloat16(v.y - __bfloat162float(h1));
    __nv_bfloat16 l2 = __float2bfloat16(v.z - __bfloat162float(h2));
    __nv_bfloat16 l3 = __float2bfloat16(v.w - __bfloat162float(h3));
    __nv_bfloat162 hA = __halves2bfloat162(h0, h1), hB = __halves2bfloat162(h2, h3);
    __nv_bfloat162 lA = __halves2bfloat162(l0, l1), lB = __halves2bfloat162(l2, l3);
    ((uint2*)hi)[i] = make_uint2(*(uint32_t*)&hA, *(uint32_t*)&hB);
    ((uint2*)lo)[i] = make_uint2(*(uint32_t*)&lA, *(uint32_t*)&lB);
}

// ---------------------------------------------------------------------------
// transpose-convert: W[k][n] fp32 -> W^T hi/lo bf16 at rows [rowoff, rowoff+1024)
// ---------------------------------------------------------------------------
__global__ void tconv_kernel(const float* __restrict__ W,
                             __nv_bfloat16* __restrict__ hiT,
                             __nv_bfloat16* __restrict__ loT, int rowoff)
{
    __shared__ float tile[32][33];
    const int n0 = blockIdx.x * 32, k0 = blockIdx.y * 32;
    const int tx = threadIdx.x, ty = threadIdx.y;   // 32 x 8
    #pragma unroll
    for (int j = 0; j < 4; j++)
        tile[ty + 8 * j][tx] = W[(size_t)(k0 + ty + 8 * j) * D_MODEL + n0 + tx];
    __syncthreads();
    #pragma unroll
    for (int j = 0; j < 4; j++) {
        float v = tile[tx][ty + 8 * j];
        __nv_bfloat16 h = __float2bfloat16(v);
        __nv_bfloat16 l = __float2bfloat16(v - __bfloat162float(h));
        size_t o = (size_t)(rowoff + n0 + ty + 8 * j) * D_MODEL + k0 + tx;
        hiT[o] = h;
        loT[o] = l;
    }
}

// ---------------------------------------------------------------------------
// Pipelined split-bf16 GEMM.  C[M,N] = A[M,K] @ B[K,N] with A as (hi,lo)[M][K]
// and B as transposed (hi,lo)[N][K].  CTA 128x128, BK=32, 256 thr (8 warps,
// warp tile 64x32), cp.async double buffer.
// ---------------------------------------------------------------------------
#define ASTR 40                               // smem row stride in halves
#define ST_MAT (128 * ASTR)                   // halves per matrix per stage
#define ST_HALVES (4 * ST_MAT)                // Ah, Al, Bh, Bl
#define GSMEM2 (2 * ST_HALVES * 2)            // bytes (2 stages)

__device__ __forceinline__ void ldm4(uint32_t r[4], uint32_t addr) {
    asm volatile("ldmatrix.sync.aligned.m8n8.x4.shared.b16 {%0,%1,%2,%3}, [%4];"
                 : "=r"(r[0]), "=r"(r[1]), "=r"(r[2]), "=r"(r[3]) : "r"(addr));
}

__device__ __forceinline__ void mma16816(float d[4], const uint32_t a[4],
                                         uint32_t b0, uint32_t b1) {
    asm volatile(
        "mma.sync.aligned.m16n8k16.row.col.f32.bf16.bf16.f32 "
        "{%0,%1,%2,%3}, {%4,%5,%6,%7}, {%8,%9}, {%0,%1,%2,%3};"
        : "+f"(d[0]), "+f"(d[1]), "+f"(d[2]), "+f"(d[3])
        : "r"(a[0]), "r"(a[1]), "r"(a[2]), "r"(a[3]), "r"(b0), "r"(b1));
}

__device__ __forceinline__ void cp16(uint32_t dst, const void* src) {
    asm volatile("cp.async.cg.shared.global [%0], [%1], 16;"
                 :: "r"(dst), "l"(src));
}

__global__ __launch_bounds__(256, 1) void gemm_tc2(
    const __nv_bfloat16* __restrict__ Ahi, const __nv_bfloat16* __restrict__ Alo,
    const __nv_bfloat16* __restrict__ BhiT, const __nv_bfloat16* __restrict__ BloT,
    float* __restrict__ C, int M, int N, int K)
{
    extern __shared__ __align__(16) __nv_bfloat16 smg[];
    const uint32_t sb = smem_u32(smg);
    const int t = threadIdx.x;
    const int wid = t >> 5, lane = t & 31;
    const int row0 = blockIdx.y * 128, col0 = blockIdx.x * 128;
    const int wm = (wid >> 2) * 64;    // warp row offset (0/64)
    const int wn = (wid & 3) * 32;     // warp col offset (0..96)

    // per-thread cp.async coords: id covers 512 rows-slots: r=id>>2, chunk=id&3
    const int r_a = (t + 0) >> 2,  c_a = t & 3;
    const int r_b = (t + 256) >> 2; // = r_a + 64

    float acc[4][4][4];
    #pragma unroll
    for (int i = 0; i < 4; i++)
        #pragma unroll
        for (int j = 0; j < 4; j++)
            #pragma unroll
            for (int q = 0; q < 4; q++) acc[i][j][q] = 0.f;

    // issue one stage of cp.async loads
    auto issue = [&](int stage, int k0) {
        uint32_t s0 = sb + (uint32_t)(stage * ST_HALVES * 2);
        uint32_t oA = (uint32_t)((r_a * ASTR + c_a * 8) * 2);
        const size_t ga = (size_t)(row0 + r_a) * K + k0 + c_a * 8;
        const size_t gb = (size_t)(col0 + r_a) * K + k0 + c_a * 8;
        cp16(s0 + oA,                   Ahi + ga);
        cp16(s0 + ST_MAT * 2 + oA,      Alo + ga);
        cp16(s0 + ST_MAT * 4 + oA,      BhiT + gb);
        cp16(s0 + ST_MAT * 6 + oA,      BloT + gb);
        uint32_t oA2 = (uint32_t)(((r_a + 64) * ASTR + c_a * 8) * 2);
        const size_t ga2 = (size_t)(row0 + r_a + 64) * K + k0 + c_a * 8;
        const size_t gb2 = (size_t)(col0 + r_a + 64) * K + k0 + c_a * 8;
        cp16(s0 + oA2,                  Ahi + ga2);
        cp16(s0 + ST_MAT * 2 + oA2,     Alo + ga2);
        cp16(s0 + ST_MAT * 4 + oA2,     BhiT + gb2);
        cp16(s0 + ST_MAT * 6 + oA2,     BloT + gb2);
        asm volatile("cp.async.commit_group;");
    };

    issue(0, 0);
    issue(1, 32);

    // ldmatrix lane addressing
    const int a_row = (lane & 7) + (lane & 8);
    const int a_col = (lane >> 4) << 3;
    const int b_row = (lane & 7) + ((lane & 16) >> 1);
    const int b_col = lane & 8;

    const int NIT = K >> 5;   // 32
    for (int it = 0; it < NIT; it++) {
        if (it + 1 < NIT) asm volatile("cp.async.wait_group 1;");
        else              asm volatile("cp.async.wait_group 0;");
        __syncthreads();

        const uint32_t s0 = sb + (uint32_t)((it & 1) * ST_HALVES * 2);
        const uint32_t sAh = s0;
        const uint32_t sAl = s0 + ST_MAT * 2;
        const uint32_t sBh = s0 + ST_MAT * 4;
        const uint32_t sBl = s0 + ST_MAT * 6;

        #pragma unroll
        for (int ks = 0; ks < 2; ks++) {
            const int kb = ks * 16;
            uint32_t ah[4][4], al[4][4], bh[2][4], bl[2][4];
            #pragma unroll
            for (int mt = 0; mt < 4; mt++) {
                uint32_t off = (uint32_t)(((wm + mt * 16 + a_row) * ASTR + kb + a_col) * 2);
                ldm4(ah[mt], sAh + off);
                ldm4(al[mt], sAl + off);
            }
            #pragma unroll
            for (int p = 0; p < 2; p++) {
                uint32_t off = (uint32_t)(((wn + p * 16 + b_row) * ASTR + kb + b_col) * 2);
                ldm4(bh[p], sBh + off);
                ldm4(bl[p], sBl + off);
            }
            #pragma unroll
            for (int mt = 0; mt < 4; mt++)
                #pragma unroll
                for (int nt = 0; nt < 4; nt++) {
                    int p = nt >> 1, s = (nt & 1) * 2;
                    mma16816(acc[mt][nt], ah[mt], bh[p][s], bh[p][s + 1]);
                    mma16816(acc[mt][nt], ah[mt], bl[p][s], bl[p][s + 1]);
                    mma16816(acc[mt][nt], al[mt], bh[p][s], bh[p][s + 1]);
                }
        }
        __syncthreads();
        if (it + 2 < NIT) issue(it & 1, (it + 2) * 32);
    }

    #pragma unroll
    for (int mt = 0; mt < 4; mt++)
        #pragma unroll
        for (int nt = 0; nt < 4; nt++) {
            int row = row0 + wm + mt * 16 + (lane >> 2);
            int col = col0 + wn + nt * 8 + (lane & 3) * 2;
            *(float2*)(C + (size_t)row * N + col) =
                make_float2(acc[mt][nt][0], acc[mt][nt][1]);
            *(float2*)(C + (size_t)(row + 8) * N + col) =
                make_float2(acc[mt][nt][2], acc[mt][nt][3]);
        }
}

// ---------------------------------------------------------------------------
// L2 normalize q,k head rows inside the fused qkv buffer. One warp per row.
// 32 rows per token: 16 q heads then 16 k heads.
// ---------------------------------------------------------------------------
__global__ void l2norm_kernel(float* __restrict__ qkv)
{
    int w    = (blockIdx.x * blockDim.x + threadIdx.x) >> 5;
    int lane = threadIdx.x & 31;
    int n    = w >> 5;
    int idx  = w & 31;
    float* p = qkv + (size_t)n * D3 + (idx >> 4) * D_MODEL + (idx & 15) * DH;
    float v0 = p[lane];
    float v1 = p[lane + 32];
    float ss = v0 * v0 + v1 * v1;
    #pragma unroll
    for (int off = 16; off; off >>= 1)
        ss += __shfl_xor_sync(0xffffffffu, ss, off);
    float s = 1.0f / fmaxf(sqrtf(ss), 1e-12f);
    p[lane]      = v0 * s;
    p[lane + 32] = v1 * s;
}

// ---------------------------------------------------------------------------
// Flash-attention (causal, cosine-sim scale=8). BM=BN=64, DH=64, 256 threads.
// Reads q/k/v from fused qkv buffer (stride 3072), writes o as hi/lo bf16.
// ---------------------------------------------------------------------------
#define FPAD 65
#define FSMEM (4 * 64 * FPAD * 4)

__global__ __launch_bounds__(256) void flash_kernel(
    const float* __restrict__ qkv,
    __nv_bfloat16* __restrict__ ohi, __nv_bfloat16* __restrict__ olo)
{
    extern __shared__ float smf[];
    float* Qs = smf;
    float* Ks = Qs + 64 * FPAD;
    float* Vs = Ks + 64 * FPAD;
    float* Ps = Vs + 64 * FPAD;

    const int qb   = blockIdx.x;
    const int head = blockIdx.y;
    const int t  = threadIdx.x;
    const int tx = t & 15;
    const int ty = t >> 4;
    const int i0 = ty * 4;
    const int j0 = tx * 4;
    const size_t hoff = (size_t)head * DH;

    const float* q = qkv + hoff;
    const float* k = qkv + D_MODEL + hoff;
    const float* v = qkv + 2 * D_MODEL + hoff;

    #pragma unroll
    for (int l = 0; l < 16; l++) {
        int idx = t + l * 256;
        int r = idx >> 6, c = idx & 63;
        Qs[r * FPAD + c] = q[(size_t)(qb * 64 + r) * D3 + c];
    }

    float m[4], lsum[4], acc[4][4];
    #pragma unroll
    for (int ii = 0; ii < 4; ii++) {
        m[ii] = -1e30f; lsum[ii] = 0.f;
        #pragma unroll
        for (int jj = 0; jj < 4; jj++) acc[ii][jj] = 0.f;
    }

    for (int jb = 0; jb <= qb; jb++) {
        __syncthreads();
        #pragma unroll
        for (int l = 0; l < 16; l++) {
            int idx = t + l * 256;
            int r = idx >> 6, c = idx & 63;
            Ks[r * FPAD + c] = k[(size_t)(jb * 64 + r) * D3 + c];
            Vs[r * FPAD + c] = v[(size_t)(jb * 64 + r) * D3 + c];
        }
        __syncthreads();

        float s[4][4];
        #pragma unroll
        for (int ii = 0; ii < 4; ii++)
            #pragma unroll
            for (int jj = 0; jj < 4; jj++) s[ii][jj] = 0.f;

        #pragma unroll 4
        for (int kk = 0; kk < 64; kk++) {
            float qf[4], kf[4];
            #pragma unroll
            for (int ii = 0; ii < 4; ii++) qf[ii] = Qs[(i0 + ii) * FPAD + kk];
            #pragma unroll
            for (int jj = 0; jj < 4; jj++) kf[jj] = Ks[(j0 + jj) * FPAD + kk];
            #pragma unroll
            for (int ii = 0; ii < 4; ii++)
                #pragma unroll
                for (int jj = 0; jj < 4; jj++)
                    s[ii][jj] = fmaf(qf[ii], kf[jj], s[ii][jj]);
        }

        #pragma unroll
        for (int ii = 0; ii < 4; ii++)
            #pragma unroll
            for (int jj = 0; jj < 4; jj++) {
                s[ii][jj] *= 8.0f;
                if (jb == qb && (j0 + jj) > (i0 + ii)) s[ii][jj] = -1e30f;
            }

        #pragma unroll
        for (int ii = 0; ii < 4; ii++) {
            float mx = fmaxf(fmaxf(s[ii][0], s[ii][1]), fmaxf(s[ii][2], s[ii][3]));
            #pragma unroll
            for (int off = 8; off; off >>= 1)
                mx = fmaxf(mx, __shfl_xor_sync(0xffffffffu, mx, off));
            float mn   = fmaxf(m[ii], mx);
            float corr = __expf(m[ii] - mn);
            m[ii] = mn;
            float rs = 0.f;
            #pragma unroll
            for (int jj = 0; jj < 4; jj++) {
                float p = __expf(s[ii][jj] - mn);
                s[ii][jj] = p;
                rs += p;
            }
            #pragma unroll
            for (int off = 8; off; off >>= 1)
                rs += __shfl_xor_sync(0xffffffffu, rs, off);
            lsum[ii] = lsum[ii] * corr + rs;
            #pragma unroll
            for (int jj = 0; jj < 4; jj++) acc[ii][jj] *= corr;
        }

        #pragma unroll
        for (int ii = 0; ii < 4; ii++)
            #pragma unroll
            for (int jj = 0; jj < 4; jj++)
                Ps[(i0 + ii) * FPAD + j0 + jj] = s[ii][jj];
        __syncthreads();

        #pragma unroll 4
        for (int j = 0; j < 64; j++) {
            float vf[4], pf[4];
            #pragma unroll
            for (int jj = 0; jj < 4; jj++) vf[jj] = Vs[j * FPAD + j0 + jj];
            #pragma unroll
            for (int ii = 0; ii < 4; ii++) pf[ii] = Ps[(i0 + ii) * FPAD + j];
            #pragma unroll
            for (int ii = 0; ii < 4; ii++)
                #pragma unroll
                for (int jj = 0; jj < 4; jj++)
                    acc[ii][jj] = fmaf(pf[ii], vf[jj], acc[ii][jj]);
        }
    }

    #pragma unroll
    for (int ii = 0; ii < 4; ii++) {
        float inv = 1.0f / lsum[ii];
        #pragma unroll
        for (int jj = 0; jj < 4; jj++) {
            float val = acc[ii][jj] * inv;
            __nv_bfloat16 h = __float2bfloat16(val);
            __nv_bfloat16 l = __float2bfloat16(val - __bfloat162float(h));
            size_t off = (size_t)(qb * 64 + i0 + ii) * D_MODEL + hoff + j0 + jj;
            ohi[off] = h;
            olo[off] = l;
        }
    }
}

// ---------------------------------------------------------------------------
extern "C" void kernel_launch(void* const* d_in, const int* in_sizes, int n_in,
                              void* d_out, int out_size)
{
    const float* x  = (const float*)d_in[0];
    const float* Wq = (const float*)d_in[1];
    const float* Wk = (const float*)d_in[2];
    const float* Wv = (const float*)d_in[3];
    const float* Wo = (const float*)d_in[4];

    float* qkv;
    __nv_bfloat16 *xhi, *xlo, *ohi, *olo, *wh, *wl;
    cudaGetSymbolAddress((void**)&qkv, g_qkv);
    cudaGetSymbolAddress((void**)&xhi, g_xhi);
    cudaGetSymbolAddress((void**)&xlo, g_xlo);
    cudaGetSymbolAddress((void**)&ohi, g_ohi);
    cudaGetSymbolAddress((void**)&olo, g_olo);
    cudaGetSymbolAddress((void**)&wh, g_wh);
    cudaGetSymbolAddress((void**)&wl, g_wl);

    cudaFuncSetAttribute(gemm_tc2,
                         cudaFuncAttributeMaxDynamicSharedMemorySize, GSMEM2);
    cudaFuncSetAttribute(flash_kernel,
                         cudaFuncAttributeMaxDynamicSharedMemorySize, FSMEM);

    const int NE4 = NSEQ * D_MODEL / 4;
    dim3 tgrid(D_MODEL / 32, D_MODEL / 32);
    dim3 tblk(32, 8);

    split_kernel<<<NE4 / 256, 256>>>(x, xhi, xlo);
    tconv_kernel<<<tgrid, tblk>>>(Wq, wh, wl, 0);
    tconv_kernel<<<tgrid, tblk>>>(Wk, wh, wl, 1024);
    tconv_kernel<<<tgrid, tblk>>>(Wv, wh, wl, 2048);

    gemm_tc2<<<dim3(D3 / 128, NSEQ / 128), 256, GSMEM2>>>(
        xhi, xlo, wh, wl, qkv, NSEQ, D3, D_MODEL);

    l2norm_kernel<<<NSEQ * 32 / 8, 256>>>(qkv);

    flash_kernel<<<dim3(NSEQ / 64, HEADS), 256, FSMEM>>>(qkv, ohi, olo);

    tconv_kernel<<<tgrid, tblk>>>(Wo, wh, wl, 0);
    gemm_tc2<<<dim3(D_MODEL / 128, NSEQ / 128), 256, GSMEM2>>>(
        ohi, olo, wh, wl, (float*)d_out, NSEQ, D_MODEL, D_MODEL);
}

// round 6
// speedup vs baseline: 2.5042x; 1.9706x over previous
#include <cuda_runtime.h>
#include <cuda_bf16.h>
#include <math.h>
#include <stdint.h>

#define D_MODEL 1024
#define D3      3072
#define NSEQ    4096
#define HEADS   16
#define DH      64

// Scratch (allocation-free rule: __device__ globals)
__device__ float g_qkv[NSEQ * D3];                  // fused q|k|v, stride 3072
__device__ __nv_bfloat16 g_xhi[NSEQ * D_MODEL];
__device__ __nv_bfloat16 g_xlo[NSEQ * D_MODEL];
__device__ __nv_bfloat16 g_qhi[NSEQ * D_MODEL];
__device__ __nv_bfloat16 g_qlo[NSEQ * D_MODEL];
__device__ __nv_bfloat16 g_khi[NSEQ * D_MODEL];
__device__ __nv_bfloat16 g_klo[NSEQ * D_MODEL];
__device__ __nv_bfloat16 g_vhi[NSEQ * D_MODEL];
__device__ __nv_bfloat16 g_vlo[NSEQ * D_MODEL];
__device__ __nv_bfloat16 g_ohi[NSEQ * D_MODEL];
__device__ __nv_bfloat16 g_olo[NSEQ * D_MODEL];
__device__ __nv_bfloat16 g_wh[D3 * D_MODEL];        // W^T hi  [N][K] (concat)
__device__ __nv_bfloat16 g_wl[D3 * D_MODEL];        // W^T lo  [N][K]

__device__ __forceinline__ uint32_t smem_u32(const void* p) {
    uint32_t a;
    asm("{ .reg .u64 t; cvta.to.shared.u64 t, %1; cvt.u32.u64 %0, t; }"
        : "=r"(a) : "l"(p));
    return a;
}

__device__ __forceinline__ void ldm4(uint32_t r[4], uint32_t addr) {
    asm volatile("ldmatrix.sync.aligned.m8n8.x4.shared.b16 {%0,%1,%2,%3}, [%4];"
                 : "=r"(r[0]), "=r"(r[1]), "=r"(r[2]), "=r"(r[3]) : "r"(addr));
}

__device__ __forceinline__ void ldm4t(uint32_t r[4], uint32_t addr) {
    asm volatile("ldmatrix.sync.aligned.m8n8.x4.trans.shared.b16 {%0,%1,%2,%3}, [%4];"
                 : "=r"(r[0]), "=r"(r[1]), "=r"(r[2]), "=r"(r[3]) : "r"(addr));
}

__device__ __forceinline__ void mma16816(float d[4], const uint32_t a[4],
                                         uint32_t b0, uint32_t b1) {
    asm volatile(
        "mma.sync.aligned.m16n8k16.row.col.f32.bf16.bf16.f32 "
        "{%0,%1,%2,%3}, {%4,%5,%6,%7}, {%8,%9}, {%0,%1,%2,%3};"
        : "+f"(d[0]), "+f"(d[1]), "+f"(d[2]), "+f"(d[3])
        : "r"(a[0]), "r"(a[1]), "r"(a[2]), "r"(a[3]), "r"(b0), "r"(b1));
}

__device__ __forceinline__ void cp16(uint32_t dst, const void* src) {
    asm volatile("cp.async.cg.shared.global [%0], [%1], 16;"
                 :: "r"(dst), "l"(src));
}

__device__ __forceinline__ uint32_t pkf(float x, float y) {
    __nv_bfloat162 h = __floats2bfloat162_rn(x, y);
    return *(uint32_t*)&h;
}

// ---------------------------------------------------------------------------
// split: fp32 -> (hi, lo) bf16, same layout. 4 elements / thread.
// ---------------------------------------------------------------------------
__global__ void split_kernel(const float* __restrict__ in,
                             __nv_bfloat16* __restrict__ hi,
                             __nv_bfloat16* __restrict__ lo)
{
    int i = blockIdx.x * blockDim.x + threadIdx.x;
    float4 v = ((const float4*)in)[i];
    __nv_bfloat16 h0 = __float2bfloat16(v.x), h1 = __float2bfloat16(v.y);
    __nv_bfloat16 h2 = __float2bfloat16(v.z), h3 = __float2bfloat16(v.w);
    float l0 = v.x - __bfloat162float(h0), l1 = v.y - __bfloat162float(h1);
    float l2 = v.z - __bfloat162float(h2), l3 = v.w - __bfloat162float(h3);
    __nv_bfloat162 hA = __halves2bfloat162(h0, h1), hB = __halves2bfloat162(h2, h3);
    ((uint2*)hi)[i] = make_uint2(*(uint32_t*)&hA, *(uint32_t*)&hB);
    ((uint2*)lo)[i] = make_uint2(pkf(l0, l1), pkf(l2, l3));
}

// ---------------------------------------------------------------------------
// transpose-convert: W[k][n] fp32 -> W^T hi/lo bf16 at rows [rowoff, +1024)
// ---------------------------------------------------------------------------
__global__ void tconv_kernel(const float* __restrict__ W,
                             __nv_bfloat16* __restrict__ hiT,
                             __nv_bfloat16* __restrict__ loT, int rowoff)
{
    __shared__ float tile[32][33];
    const int n0 = blockIdx.x * 32, k0 = blockIdx.y * 32;
    const int tx = threadIdx.x, ty = threadIdx.y;   // 32 x 8
    #pragma unroll
    for (int j = 0; j < 4; j++)
        tile[ty + 8 * j][tx] = W[(size_t)(k0 + ty + 8 * j) * D_MODEL + n0 + tx];
    __syncthreads();
    #pragma unroll
    for (int j = 0; j < 4; j++) {
        float v = tile[tx][ty + 8 * j];
        __nv_bfloat16 h = __float2bfloat16(v);
        __nv_bfloat16 l = __float2bfloat16(v - __bfloat162float(h));
        size_t o = (size_t)(rowoff + n0 + ty + 8 * j) * D_MODEL + k0 + tx;
        hiT[o] = h;
        loT[o] = l;
    }
}

// ---------------------------------------------------------------------------
// Pipelined split-bf16 GEMM.  C[M,N] = A[M,K] @ B[K,N].  CTA 128x128, BK=32.
// ---------------------------------------------------------------------------
#define ASTR 40
#define ST_MAT (128 * ASTR)
#define ST_HALVES (4 * ST_MAT)
#define GSMEM2 (2 * ST_HALVES * 2)

__global__ __launch_bounds__(256, 1) void gemm_tc2(
    const __nv_bfloat16* __restrict__ Ahi, const __nv_bfloat16* __restrict__ Alo,
    const __nv_bfloat16* __restrict__ BhiT, const __nv_bfloat16* __restrict__ BloT,
    float* __restrict__ C, int M, int N, int K)
{
    extern __shared__ __align__(16) __nv_bfloat16 smg[];
    const uint32_t sb = smem_u32(smg);
    const int t = threadIdx.x;
    const int wid = t >> 5, lane = t & 31;
    const int row0 = blockIdx.y * 128, col0 = blockIdx.x * 128;
    const int wm = (wid >> 2) * 64;
    const int wn = (wid & 3) * 32;

    const int r_a = t >> 2, c_a = t & 3;

    float acc[4][4][4];
    #pragma unroll
    for (int i = 0; i < 4; i++)
        #pragma unroll
        for (int j = 0; j < 4; j++)
            #pragma unroll
            for (int q = 0; q < 4; q++) acc[i][j][q] = 0.f;

    auto issue = [&](int stage, int k0) {
        uint32_t s0 = sb + (uint32_t)(stage * ST_HALVES * 2);
        uint32_t oA = (uint32_t)((r_a * ASTR + c_a * 8) * 2);
        const size_t ga = (size_t)(row0 + r_a) * K + k0 + c_a * 8;
        const size_t gb = (size_t)(col0 + r_a) * K + k0 + c_a * 8;
        cp16(s0 + oA,              Ahi + ga);
        cp16(s0 + ST_MAT * 2 + oA, Alo + ga);
        cp16(s0 + ST_MAT * 4 + oA, BhiT + gb);
        cp16(s0 + ST_MAT * 6 + oA, BloT + gb);
        uint32_t oA2 = (uint32_t)(((r_a + 64) * ASTR + c_a * 8) * 2);
        const size_t ga2 = (size_t)(row0 + r_a + 64) * K + k0 + c_a * 8;
        const size_t gb2 = (size_t)(col0 + r_a + 64) * K + k0 + c_a * 8;
        cp16(s0 + oA2,              Ahi + ga2);
        cp16(s0 + ST_MAT * 2 + oA2, Alo + ga2);
        cp16(s0 + ST_MAT * 4 + oA2, BhiT + gb2);
        cp16(s0 + ST_MAT * 6 + oA2, BloT + gb2);
        asm volatile("cp.async.commit_group;");
    };

    issue(0, 0);
    issue(1, 32);

    const int a_row = (lane & 7) + (lane & 8);
    const int a_col = (lane >> 4) << 3;
    const int b_row = (lane & 7) + ((lane & 16) >> 1);
    const int b_col = lane & 8;

    const int NIT = K >> 5;
    for (int it = 0; it < NIT; it++) {
        if (it + 1 < NIT) asm volatile("cp.async.wait_group 1;");
        else              asm volatile("cp.async.wait_group 0;");
        __syncthreads();

        const uint32_t s0 = sb + (uint32_t)((it & 1) * ST_HALVES * 2);
        const uint32_t sAh = s0;
        const uint32_t sAl = s0 + ST_MAT * 2;
        const uint32_t sBh = s0 + ST_MAT * 4;
        const uint32_t sBl = s0 + ST_MAT * 6;

        #pragma unroll
        for (int ks = 0; ks < 2; ks++) {
            const int kb = ks * 16;
            uint32_t ah[4][4], al[4][4], bh[2][4], bl[2][4];
            #pragma unroll
            for (int mt = 0; mt < 4; mt++) {
                uint32_t off = (uint32_t)(((wm + mt * 16 + a_row) * ASTR + kb + a_col) * 2);
                ldm4(ah[mt], sAh + off);
                ldm4(al[mt], sAl + off);
            }
            #pragma unroll
            for (int p = 0; p < 2; p++) {
                uint32_t off = (uint32_t)(((wn + p * 16 + b_row) * ASTR + kb + b_col) * 2);
                ldm4(bh[p], sBh + off);
                ldm4(bl[p], sBl + off);
            }
            #pragma unroll
            for (int mt = 0; mt < 4; mt++)
                #pragma unroll
                for (int nt = 0; nt < 4; nt++) {
                    int p = nt >> 1, s = (nt & 1) * 2;
                    mma16816(acc[mt][nt], ah[mt], bh[p][s], bh[p][s + 1]);
                    mma16816(acc[mt][nt], ah[mt], bl[p][s], bl[p][s + 1]);
                    mma16816(acc[mt][nt], al[mt], bh[p][s], bh[p][s + 1]);
                }
        }
        __syncthreads();
        if (it + 2 < NIT) issue(it & 1, (it + 2) * 32);
    }

    #pragma unroll
    for (int mt = 0; mt < 4; mt++)
        #pragma unroll
        for (int nt = 0; nt < 4; nt++) {
            int row = row0 + wm + mt * 16 + (lane >> 2);
            int col = col0 + wn + nt * 8 + (lane & 3) * 2;
            *(float2*)(C + (size_t)row * N + col) =
                make_float2(acc[mt][nt][0], acc[mt][nt][1]);
            *(float2*)(C + (size_t)(row + 8) * N + col) =
                make_float2(acc[mt][nt][2], acc[mt][nt][3]);
        }
}

// ---------------------------------------------------------------------------
// l2norm (q,k) + bf16 hi/lo split of q,k,v from the fused qkv buffer.
// One warp per 64-wide head row; 48 slots per token (16 q, 16 k, 16 v).
// ---------------------------------------------------------------------------
__global__ void l2split_kernel(const float* __restrict__ qkv,
                               __nv_bfloat16* __restrict__ qhi, __nv_bfloat16* __restrict__ qlo,
                               __nv_bfloat16* __restrict__ khi, __nv_bfloat16* __restrict__ klo,
                               __nv_bfloat16* __restrict__ vhi, __nv_bfloat16* __restrict__ vlo)
{
    int w    = (blockIdx.x * blockDim.x + threadIdx.x) >> 5;
    int lane = threadIdx.x & 31;
    int n    = w / 48;
    int slot = w % 48;
    const float* p = qkv + (size_t)n * D3 + slot * 64;
    float2 vv = ((const float2*)p)[lane];

    if (slot < 32) {
        float ss = vv.x * vv.x + vv.y * vv.y;
        #pragma unroll
        for (int off = 16; off; off >>= 1)
            ss += __shfl_xor_sync(0xffffffffu, ss, off);
        float s = 1.0f / fmaxf(sqrtf(ss), 1e-12f);
        vv.x *= s;
        vv.y *= s;
    }
    __nv_bfloat16 h0 = __float2bfloat16(vv.x), h1 = __float2bfloat16(vv.y);
    float l0 = vv.x - __bfloat162float(h0), l1 = vv.y - __bfloat162float(h1);
    __nv_bfloat162 hp = __halves2bfloat162(h0, h1);

    size_t d = ((size_t)n * D_MODEL + (slot & 15) * 64 + lane * 2) / 2;
    __nv_bfloat16* dh = (slot < 16) ? qhi : (slot < 32) ? khi : vhi;
    __nv_bfloat16* dl = (slot < 16) ? qlo : (slot < 32) ? klo : vlo;
    ((uint32_t*)dh)[d] = *(uint32_t*)&hp;
    ((uint32_t*)dl)[d] = pkf(l0, l1);
}

// ---------------------------------------------------------------------------
// Tensor-core flash attention (causal, scale=8). BM=64 (4 warps x m16),
// BN=64, DH=64, cp.async double-buffered K/V hi/lo, bf16-split everywhere.
// ---------------------------------------------------------------------------
#define VSTR 72
#define MATB (64 * VSTR * 2)          // bytes per matrix
#define FSTGB (4 * MATB)              // bytes per stage
#define FSMEM2 (2 * FSTGB)

__global__ __launch_bounds__(128) void flash_tc(
    const __nv_bfloat16* __restrict__ qhi, const __nv_bfloat16* __restrict__ qlo,
    const __nv_bfloat16* __restrict__ khi, const __nv_bfloat16* __restrict__ klo,
    const __nv_bfloat16* __restrict__ vhi, const __nv_bfloat16* __restrict__ vlo,
    __nv_bfloat16* __restrict__ ohi, __nv_bfloat16* __restrict__ olo)
{
    extern __shared__ __align__(16) __nv_bfloat16 smx[];
    const uint32_t sb = smem_u32(smx);
    const int qb = blockIdx.x, head = blockIdx.y;
    const int t = threadIdx.x, w = t >> 5, lane = t & 31;
    const int hcol = head * DH;

    // cp.async coords: thread covers (row = t>>1, 32-half chunk = t&1)
    const int lr = t >> 1, lh = (t & 1) * 32;

    auto ldstage = [&](uint32_t base, const __nv_bfloat16* mhi,
                       const __nv_bfloat16* mlo, int seq0) {
        const size_t g = (size_t)(seq0 + lr) * D_MODEL + hcol + lh;
        uint32_t d = base + (uint32_t)((lr * VSTR + lh) * 2);
        #pragma unroll
        for (int q2 = 0; q2 < 4; q2++) {
            cp16(d + q2 * 16,        mhi + g + q2 * 8);
            cp16(d + MATB + q2 * 16, mlo + g + q2 * 8);
        }
    };

    // ---- stage Q through stage-0 K slots, load A-fragments
    ldstage(sb, qhi, qlo, qb * 64);
    asm volatile("cp.async.commit_group;");
    asm volatile("cp.async.wait_group 0;");
    __syncthreads();

    const int a_row = (lane & 7) + (lane & 8);
    const int a_col = (lane >> 4) << 3;
    uint32_t ah[4][4], al[4][4];
    #pragma unroll
    for (int kc = 0; kc < 4; kc++) {
        uint32_t off = (uint32_t)(((w * 16 + a_row) * VSTR + kc * 16 + a_col) * 2);
        ldm4(ah[kc], sb + off);
        ldm4(al[kc], sb + MATB + off);
    }
    __syncthreads();

    // ---- preload KV stages
    auto issue = [&](int stage, int jb) {
        uint32_t s0 = sb + (uint32_t)(stage * FSTGB);
        ldstage(s0,            khi, klo, jb * 64);
        ldstage(s0 + 2 * MATB, vhi, vlo, jb * 64);
        asm volatile("cp.async.commit_group;");
    };
    issue(0, 0);
    if (qb >= 1) issue(1, 1);

    float o[8][4];
    #pragma unroll
    for (int i = 0; i < 8; i++)
        #pragma unroll
        for (int j = 0; j < 4; j++) o[i][j] = 0.f;
    float m0 = -1e30f, m1 = -1e30f, l0 = 0.f, l1 = 0.f;

    const int b_row = (lane & 7) + ((lane & 16) >> 1);
    const int b_col = lane & 8;
    const int vg = lane >> 3;                 // trans-ldm group
    const int v_row = (vg & 1) * 8 + (lane & 7);
    const int v_col = (vg >> 1) * 8;
    const int myrow0 = qb * 64 + w * 16 + (lane >> 2);

    for (int jb = 0; jb <= qb; jb++) {
        if (jb < qb) asm volatile("cp.async.wait_group 1;");
        else         asm volatile("cp.async.wait_group 0;");
        __syncthreads();

        const uint32_t s0 = sb + (uint32_t)((jb & 1) * FSTGB);
        const uint32_t pKh = s0, pKl = s0 + MATB;
        const uint32_t pVh = s0 + 2 * MATB, pVl = s0 + 3 * MATB;

        // ---- S = Q K^T (3 split passes)
        float s[8][4];
        #pragma unroll
        for (int i = 0; i < 8; i++)
            #pragma unroll
            for (int j = 0; j < 4; j++) s[i][j] = 0.f;

        #pragma unroll
        for (int kc = 0; kc < 4; kc++) {
            uint32_t bh[4][4], bl[4][4];
            #pragma unroll
            for (int p = 0; p < 4; p++) {
                uint32_t off = (uint32_t)(((p * 16 + b_row) * VSTR + kc * 16 + b_col) * 2);
                ldm4(bh[p], pKh + off);
                ldm4(bl[p], pKl + off);
            }
            #pragma unroll
            for (int nt = 0; nt < 8; nt++) {
                int p = nt >> 1, si = (nt & 1) * 2;
                mma16816(s[nt], ah[kc], bh[p][si], bh[p][si + 1]);
                mma16816(s[nt], ah[kc], bl[p][si], bl[p][si + 1]);
                mma16816(s[nt], al[kc], bh[p][si], bh[p][si + 1]);
            }
        }

        // ---- scale + causal mask (only diagonal block needs it)
        if (jb == qb) {
            #pragma unroll
            for (int nt = 0; nt < 8; nt++) {
                int colb = jb * 64 + nt * 8 + (lane & 3) * 2;
                #pragma unroll
                for (int c = 0; c < 4; c++) {
                    int col = colb + (c & 1);
                    int row = myrow0 + (c >> 1) * 8;
                    s[nt][c] = (col > row) ? -1e30f : s[nt][c] * 8.0f;
                }
            }
        } else {
            #pragma unroll
            for (int nt = 0; nt < 8; nt++)
                #pragma unroll
                for (int c = 0; c < 4; c++) s[nt][c] *= 8.0f;
        }

        // ---- online softmax on fragments
        float mx0 = -1e30f, mx1 = -1e30f;
        #pragma unroll
        for (int nt = 0; nt < 8; nt++) {
            mx0 = fmaxf(mx0, fmaxf(s[nt][0], s[nt][1]));
            mx1 = fmaxf(mx1, fmaxf(s[nt][2], s[nt][3]));
        }
        mx0 = fmaxf(mx0, __shfl_xor_sync(0xffffffffu, mx0, 1));
        mx0 = fmaxf(mx0, __shfl_xor_sync(0xffffffffu, mx0, 2));
        mx1 = fmaxf(mx1, __shfl_xor_sync(0xffffffffu, mx1, 1));
        mx1 = fmaxf(mx1, __shfl_xor_sync(0xffffffffu, mx1, 2));
        float mn0 = fmaxf(m0, mx0), mn1 = fmaxf(m1, mx1);
        float c0 = __expf(m0 - mn0), c1 = __expf(m1 - mn1);
        m0 = mn0; m1 = mn1;

        float rs0 = 0.f, rs1 = 0.f;
        #pragma unroll
        for (int nt = 0; nt < 8; nt++) {
            s[nt][0] = __expf(s[nt][0] - mn0);
            s[nt][1] = __expf(s[nt][1] - mn0);
            s[nt][2] = __expf(s[nt][2] - mn1);
            s[nt][3] = __expf(s[nt][3] - mn1);
            rs0 += s[nt][0] + s[nt][1];
            rs1 += s[nt][2] + s[nt][3];
        }
        rs0 += __shfl_xor_sync(0xffffffffu, rs0, 1);
        rs0 += __shfl_xor_sync(0xffffffffu, rs0, 2);
        rs1 += __shfl_xor_sync(0xffffffffu, rs1, 1);
        rs1 += __shfl_xor_sync(0xffffffffu, rs1, 2);
        l0 = l0 * c0 + rs0;
        l1 = l1 * c1 + rs1;
        #pragma unroll
        for (int nt = 0; nt < 8; nt++) {
            o[nt][0] *= c0; o[nt][1] *= c0;
            o[nt][2] *= c1; o[nt][3] *= c1;
        }

        // ---- O += P V (3 split passes), P split in regs
        #pragma unroll
        for (int kt = 0; kt < 4; kt++) {
            uint32_t pa_h[4], pa_l[4];
            #pragma unroll
            for (int hh = 0; hh < 2; hh++) {
                const float* sv = s[2 * kt + hh];
                __nv_bfloat16 h0 = __float2bfloat16(sv[0]);
                __nv_bfloat16 h1 = __float2bfloat16(sv[1]);
                __nv_bfloat16 h2 = __float2bfloat16(sv[2]);
                __nv_bfloat16 h3 = __float2bfloat16(sv[3]);
                __nv_bfloat162 p01 = __halves2bfloat162(h0, h1);
                __nv_bfloat162 p23 = __halves2bfloat162(h2, h3);
                pa_h[2 * hh]     = *(uint32_t*)&p01;
                pa_h[2 * hh + 1] = *(uint32_t*)&p23;
                pa_l[2 * hh]     = pkf(sv[0] - __bfloat162float(h0),
                                       sv[1] - __bfloat162float(h1));
                pa_l[2 * hh + 1] = pkf(sv[2] - __bfloat162float(h2),
                                       sv[3] - __bfloat162float(h3));
            }
            // reorder to a-frag: {a0,a1,a2,a3} = {r c01 of tile0, r+8 tile0, tile1, tile1+8}
            uint32_t afh[4] = {pa_h[0], pa_h[1], pa_h[2], pa_h[3]};
            uint32_t afl[4] = {pa_l[0], pa_l[1], pa_l[2], pa_l[3]};

            #pragma unroll
            for (int nc = 0; nc < 4; nc++) {
                uint32_t off = (uint32_t)(((kt * 16 + v_row) * VSTR + nc * 16 + v_col) * 2);
                uint32_t vbh[4], vbl[4];
                ldm4t(vbh, pVh + off);
                ldm4t(vbl, pVl + off);
                mma16816(o[2 * nc],     afh, vbh[0], vbh[1]);
                mma16816(o[2 * nc],     afh, vbl[0], vbl[1]);
                mma16816(o[2 * nc],     afl, vbh[0], vbh[1]);
                mma16816(o[2 * nc + 1], afh, vbh[2], vbh[3]);
                mma16816(o[2 * nc + 1], afh, vbl[2], vbl[3]);
                mma16816(o[2 * nc + 1], afl, vbh[2], vbh[3]);
            }
        }

        __syncthreads();
        if (jb + 2 <= qb) issue(jb & 1, jb + 2);
    }

    // ---- epilogue: normalize, split, store bf16 hi/lo
    float inv0 = 1.0f / l0, inv1 = 1.0f / l1;
    #pragma unroll
    for (int nt = 0; nt < 8; nt++) {
        int col = hcol + nt * 8 + (lane & 3) * 2;
        {
            float x = o[nt][0] * inv0, y = o[nt][1] * inv0;
            __nv_bfloat16 hx = __float2bfloat16(x), hy = __float2bfloat16(y);
            __nv_bfloat162 hp = __halves2bfloat162(hx, hy);
            size_t d = ((size_t)myrow0 * D_MODEL + col) / 2;
            ((uint32_t*)ohi)[d] = *(uint32_t*)&hp;
            ((uint32_t*)olo)[d] = pkf(x - __bfloat162float(hx), y - __bfloat162float(hy));
        }
        {
            float x = o[nt][2] * inv1, y = o[nt][3] * inv1;
            __nv_bfloat16 hx = __float2bfloat16(x), hy = __float2bfloat16(y);
            __nv_bfloat162 hp = __halves2bfloat162(hx, hy);
            size_t d = ((size_t)(myrow0 + 8) * D_MODEL + col) / 2;
            ((uint32_t*)ohi)[d] = *(uint32_t*)&hp;
            ((uint32_t*)olo)[d] = pkf(x - __bfloat162float(hx), y - __bfloat162float(hy));
        }
    }
}

// ---------------------------------------------------------------------------
extern "C" void kernel_launch(void* const* d_in, const int* in_sizes, int n_in,
                              void* d_out, int out_size)
{
    const float* x  = (const float*)d_in[0];
    const float* Wq = (const float*)d_in[1];
    const float* Wk = (const float*)d_in[2];
    const float* Wv = (const float*)d_in[3];
    const float* Wo = (const float*)d_in[4];

    float* qkv;
    __nv_bfloat16 *xhi, *xlo, *qhi, *qlo, *khi, *klo, *vhi, *vlo, *ohi, *olo, *wh, *wl;
    cudaGetSymbolAddress((void**)&qkv, g_qkv);
    cudaGetSymbolAddress((void**)&xhi, g_xhi);
    cudaGetSymbolAddress((void**)&xlo, g_xlo);
    cudaGetSymbolAddress((void**)&qhi, g_qhi);
    cudaGetSymbolAddress((void**)&qlo, g_qlo);
    cudaGetSymbolAddress((void**)&khi, g_khi);
    cudaGetSymbolAddress((void**)&klo, g_klo);
    cudaGetSymbolAddress((void**)&vhi, g_vhi);
    cudaGetSymbolAddress((void**)&vlo, g_vlo);
    cudaGetSymbolAddress((void**)&ohi, g_ohi);
    cudaGetSymbolAddress((void**)&olo, g_olo);
    cudaGetSymbolAddress((void**)&wh, g_wh);
    cudaGetSymbolAddress((void**)&wl, g_wl);

    cudaFuncSetAttribute(gemm_tc2,
                         cudaFuncAttributeMaxDynamicSharedMemorySize, GSMEM2);
    cudaFuncSetAttribute(flash_tc,
                         cudaFuncAttributeMaxDynamicSharedMemorySize, FSMEM2);

    const int NE4 = NSEQ * D_MODEL / 4;
    dim3 tgrid(D_MODEL / 32, D_MODEL / 32);
    dim3 tblk(32, 8);

    split_kernel<<<NE4 / 256, 256>>>(x, xhi, xlo);
    tconv_kernel<<<tgrid, tblk>>>(Wq, wh, wl, 0);
    tconv_kernel<<<tgrid, tblk>>>(Wk, wh, wl, 1024);
    tconv_kernel<<<tgrid, tblk>>>(Wv, wh, wl, 2048);

    gemm_tc2<<<dim3(D3 / 128, NSEQ / 128), 256, GSMEM2>>>(
        xhi, xlo, wh, wl, qkv, NSEQ, D3, D_MODEL);

    l2split_kernel<<<NSEQ * 48 / 8, 256>>>(qkv, qhi, qlo, khi, klo, vhi, vlo);

    flash_tc<<<dim3(NSEQ / 64, HEADS), 128, FSMEM2>>>(
        qhi, qlo, khi, klo, vhi, vlo, ohi, olo);

    tconv_kernel<<<tgrid, tblk>>>(Wo, wh, wl, 0);
    gemm_tc2<<<dim3(D_MODEL / 128, NSEQ / 128), 256, GSMEM2>>>(
        ohi, olo, wh, wl, (float*)d_out, NSEQ, D_MODEL, D_MODEL);
}

// round 9
// speedup vs baseline: 2.6660x; 1.0646x over previous
#include <cuda_runtime.h>
#include <cuda_bf16.h>
#include <math.h>
#include <stdint.h>

#define D_MODEL 1024
#define D3      3072
#define NSEQ    4096
#define HEADS   16
#define DH      64

// Scratch (allocation-free rule: __device__ globals)
__device__ float g_qkv[NSEQ * D3];                  // fused q|k|v, stride 3072
__device__ __nv_bfloat16 g_xhi[NSEQ * D_MODEL];
__device__ __nv_bfloat16 g_xlo[NSEQ * D_MODEL];
__device__ __nv_bfloat16 g_qhi[NSEQ * D_MODEL];
__device__ __nv_bfloat16 g_qlo[NSEQ * D_MODEL];
__device__ __nv_bfloat16 g_khi[NSEQ * D_MODEL];
__device__ __nv_bfloat16 g_klo[NSEQ * D_MODEL];
__device__ __nv_bfloat16 g_vhi[NSEQ * D_MODEL];
__device__ __nv_bfloat16 g_vlo[NSEQ * D_MODEL];
__device__ __nv_bfloat16 g_ohi[NSEQ * D_MODEL];
__device__ __nv_bfloat16 g_olo[NSEQ * D_MODEL];
__device__ __nv_bfloat16 g_wh[D3 * D_MODEL];        // W^T hi  [N][K] (concat)
__device__ __nv_bfloat16 g_wl[D3 * D_MODEL];        // W^T lo  [N][K]

__device__ __forceinline__ uint32_t smem_u32(const void* p) {
    uint32_t a;
    asm("{ .reg .u64 t; cvta.to.shared.u64 t, %1; cvt.u32.u64 %0, t; }"
        : "=r"(a) : "l"(p));
    return a;
}

__device__ __forceinline__ void ldm4(uint32_t r[4], uint32_t addr) {
    asm volatile("ldmatrix.sync.aligned.m8n8.x4.shared.b16 {%0,%1,%2,%3}, [%4];"
                 : "=r"(r[0]), "=r"(r[1]), "=r"(r[2]), "=r"(r[3]) : "r"(addr));
}

__device__ __forceinline__ void ldm4t(uint32_t r[4], uint32_t addr) {
    asm volatile("ldmatrix.sync.aligned.m8n8.x4.trans.shared.b16 {%0,%1,%2,%3}, [%4];"
                 : "=r"(r[0]), "=r"(r[1]), "=r"(r[2]), "=r"(r[3]) : "r"(addr));
}

__device__ __forceinline__ void mma16816(float d[4], const uint32_t a[4],
                                         uint32_t b0, uint32_t b1) {
    asm volatile(
        "mma.sync.aligned.m16n8k16.row.col.f32.bf16.bf16.f32 "
        "{%0,%1,%2,%3}, {%4,%5,%6,%7}, {%8,%9}, {%0,%1,%2,%3};"
        : "+f"(d[0]), "+f"(d[1]), "+f"(d[2]), "+f"(d[3])
        : "r"(a[0]), "r"(a[1]), "r"(a[2]), "r"(a[3]), "r"(b0), "r"(b1));
}

__device__ __forceinline__ void cp16(uint32_t dst, const void* src) {
    asm volatile("cp.async.cg.shared.global [%0], [%1], 16;"
                 :: "r"(dst), "l"(src));
}

__device__ __forceinline__ uint32_t pkf(float x, float y) {
    __nv_bfloat162 h = __floats2bfloat162_rn(x, y);
    return *(uint32_t*)&h;
}

// ---------------------------------------------------------------------------
// split: fp32 -> (hi, lo) bf16, same layout. 4 elements / thread.
// ---------------------------------------------------------------------------
__global__ void split_kernel(const float* __restrict__ in,
                             __nv_bfloat16* __restrict__ hi,
                             __nv_bfloat16* __restrict__ lo)
{
    int i = blockIdx.x * blockDim.x + threadIdx.x;
    float4 v = ((const float4*)in)[i];
    __nv_bfloat16 h0 = __float2bfloat16(v.x), h1 = __float2bfloat16(v.y);
    __nv_bfloat16 h2 = __float2bfloat16(v.z), h3 = __float2bfloat16(v.w);
    float l0 = v.x - __bfloat162float(h0), l1 = v.y - __bfloat162float(h1);
    float l2 = v.z - __bfloat162float(h2), l3 = v.w - __bfloat162float(h3);
    __nv_bfloat162 hA = __halves2bfloat162(h0, h1), hB = __halves2bfloat162(h2, h3);
    ((uint2*)hi)[i] = make_uint2(*(uint32_t*)&hA, *(uint32_t*)&hB);
    ((uint2*)lo)[i] = make_uint2(pkf(l0, l1), pkf(l2, l3));
}

// ---------------------------------------------------------------------------
// transpose-convert: W[k][n] fp32 -> W^T hi/lo bf16 at rows [rowoff, +1024)
// ---------------------------------------------------------------------------
__global__ void tconv_kernel(const float* __restrict__ W,
                             __nv_bfloat16* __restrict__ hiT,
                             __nv_bfloat16* __restrict__ loT, int rowoff)
{
    __shared__ float tile[32][33];
    const int n0 = blockIdx.x * 32, k0 = blockIdx.y * 32;
    const int tx = threadIdx.x, ty = threadIdx.y;   // 32 x 8
    #pragma unroll
    for (int j = 0; j < 4; j++)
        tile[ty + 8 * j][tx] = W[(size_t)(k0 + ty + 8 * j) * D_MODEL + n0 + tx];
    __syncthreads();
    #pragma unroll
    for (int j = 0; j < 4; j++) {
        float v = tile[tx][ty + 8 * j];
        __nv_bfloat16 h = __float2bfloat16(v);
        __nv_bfloat16 l = __float2bfloat16(v - __bfloat162float(h));
        size_t o = (size_t)(rowoff + n0 + ty + 8 * j) * D_MODEL + k0 + tx;
        hiT[o] = h;
        loT[o] = l;
    }
}

// ---------------------------------------------------------------------------
// Pipelined split-bf16 GEMM.  C[M,N] = A[M,K] @ B[K,N].  CTA 128x128, BK=32,
// 3-stage cp.async pipeline, ONE __syncthreads per K-iteration.
// ---------------------------------------------------------------------------
#define ASTR 40
#define ST_MAT (128 * ASTR)
#define ST_HALVES (4 * ST_MAT)
#define STG_BYTES (ST_HALVES * 2)
#define GSMEM3 (3 * STG_BYTES)

__global__ __launch_bounds__(256, 1) void gemm_tc2(
    const __nv_bfloat16* __restrict__ Ahi, const __nv_bfloat16* __restrict__ Alo,
    const __nv_bfloat16* __restrict__ BhiT, const __nv_bfloat16* __restrict__ BloT,
    float* __restrict__ C, int M, int N, int K)
{
    extern __shared__ __align__(16) __nv_bfloat16 smg[];
    const uint32_t sb = smem_u32(smg);
    const int t = threadIdx.x;
    const int wid = t >> 5, lane = t & 31;
    const int row0 = blockIdx.y * 128, col0 = blockIdx.x * 128;
    const int wm = (wid >> 2) * 64;
    const int wn = (wid & 3) * 32;

    const int r_a = t >> 2, c_a = t & 3;

    float acc[4][4][4];
    #pragma unroll
    for (int i = 0; i < 4; i++)
        #pragma unroll
        for (int j = 0; j < 4; j++)
            #pragma unroll
            for (int q = 0; q < 4; q++) acc[i][j][q] = 0.f;

    auto issue = [&](int stage, int k0) {
        uint32_t s0 = sb + (uint32_t)(stage * STG_BYTES);
        uint32_t oA = (uint32_t)((r_a * ASTR + c_a * 8) * 2);
        const size_t ga = (size_t)(row0 + r_a) * K + k0 + c_a * 8;
        const size_t gb = (size_t)(col0 + r_a) * K + k0 + c_a * 8;
        cp16(s0 + oA,              Ahi + ga);
        cp16(s0 + ST_MAT * 2 + oA, Alo + ga);
        cp16(s0 + ST_MAT * 4 + oA, BhiT + gb);
        cp16(s0 + ST_MAT * 6 + oA, BloT + gb);
        uint32_t oA2 = (uint32_t)(((r_a + 64) * ASTR + c_a * 8) * 2);
        const size_t ga2 = (size_t)(row0 + r_a + 64) * K + k0 + c_a * 8;
        const size_t gb2 = (size_t)(col0 + r_a + 64) * K + k0 + c_a * 8;
        cp16(s0 + oA2,              Ahi + ga2);
        cp16(s0 + ST_MAT * 2 + oA2, Alo + ga2);
        cp16(s0 + ST_MAT * 4 + oA2, BhiT + gb2);
        cp16(s0 + ST_MAT * 6 + oA2, BloT + gb2);
        asm volatile("cp.async.commit_group;");
    };

    issue(0, 0);
    issue(1, 32);

    const int a_row = (lane & 7) + (lane & 8);
    const int a_col = (lane >> 4) << 3;
    const int b_row = (lane & 7) + ((lane & 16) >> 1);
    const int b_col = lane & 8;

    const int NIT = K >> 5;          // 32
    int stage = 0;
    for (int it = 0; it < NIT; it++) {
        asm volatile("cp.async.wait_group 1;");
        __syncthreads();

        const uint32_t s0 = sb + (uint32_t)(stage * STG_BYTES);
        const uint32_t sAh = s0;
        const uint32_t sAl = s0 + ST_MAT * 2;
        const uint32_t sBh = s0 + ST_MAT * 4;
        const uint32_t sBl = s0 + ST_MAT * 6;

        #pragma unroll
        for (int ks = 0; ks < 2; ks++) {
            const int kb = ks * 16;
            uint32_t ah[4][4], al[4][4], bh[2][4], bl[2][4];
            #pragma unroll
            for (int mt = 0; mt < 4; mt++) {
                uint32_t off = (uint32_t)(((wm + mt * 16 + a_row) * ASTR + kb + a_col) * 2);
                ldm4(ah[mt], sAh + off);
                ldm4(al[mt], sAl + off);
            }
            #pragma unroll
            for (int p = 0; p < 2; p++) {
                uint32_t off = (uint32_t)(((wn + p * 16 + b_row) * ASTR + kb + b_col) * 2);
                ldm4(bh[p], sBh + off);
                ldm4(bl[p], sBl + off);
            }
            #pragma unroll
            for (int mt = 0; mt < 4; mt++)
                #pragma unroll
                for (int nt = 0; nt < 4; nt++) {
                    int p = nt >> 1, s = (nt & 1) * 2;
                    mma16816(acc[mt][nt], ah[mt], bh[p][s], bh[p][s + 1]);
                    mma16816(acc[mt][nt], ah[mt], bl[p][s], bl[p][s + 1]);
                    mma16816(acc[mt][nt], al[mt], bh[p][s], bh[p][s + 1]);
                }
        }

        // issue stage it+2 into the buffer consumed at it-1 (safe post-barrier)
        if (it + 2 < NIT) {
            int ns = stage + 2;
            if (ns >= 3) ns -= 3;
            issue(ns, (it + 2) * 32);
        }
        stage = (stage + 1 == 3) ? 0 : stage + 1;
    }

    #pragma unroll
    for (int mt = 0; mt < 4; mt++)
        #pragma unroll
        for (int nt = 0; nt < 4; nt++) {
            int row = row0 + wm + mt * 16 + (lane >> 2);
            int col = col0 + wn + nt * 8 + (lane & 3) * 2;
            *(float2*)(C + (size_t)row * N + col) =
                make_float2(acc[mt][nt][0], acc[mt][nt][1]);
            *(float2*)(C + (size_t)(row + 8) * N + col) =
                make_float2(acc[mt][nt][2], acc[mt][nt][3]);
        }
}

// ---------------------------------------------------------------------------
// l2norm (q,k) + bf16 hi/lo split of q,k,v from the fused qkv buffer.
// ---------------------------------------------------------------------------
__global__ void l2split_kernel(const float* __restrict__ qkv,
                               __nv_bfloat16* __restrict__ qhi, __nv_bfloat16* __restrict__ qlo,
                               __nv_bfloat16* __restrict__ khi, __nv_bfloat16* __restrict__ klo,
                               __nv_bfloat16* __restrict__ vhi, __nv_bfloat16* __restrict__ vlo)
{
    int w    = (blockIdx.x * blockDim.x + threadIdx.x) >> 5;
    int lane = threadIdx.x & 31;
    int n    = w / 48;
    int slot = w % 48;
    const float* p = qkv + (size_t)n * D3 + slot * 64;
    float2 vv = ((const float2*)p)[lane];

    if (slot < 32) {
        float ss = vv.x * vv.x + vv.y * vv.y;
        #pragma unroll
        for (int off = 16; off; off >>= 1)
            ss += __shfl_xor_sync(0xffffffffu, ss, off);
        float s = 1.0f / fmaxf(sqrtf(ss), 1e-12f);
        vv.x *= s;
        vv.y *= s;
    }
    __nv_bfloat16 h0 = __float2bfloat16(vv.x), h1 = __float2bfloat16(vv.y);
    float l0 = vv.x - __bfloat162float(h0), l1 = vv.y - __bfloat162float(h1);
    __nv_bfloat162 hp = __halves2bfloat162(h0, h1);

    size_t d = ((size_t)n * D_MODEL + (slot & 15) * 64 + lane * 2) / 2;
    __nv_bfloat16* dh = (slot < 16) ? qhi : (slot < 32) ? khi : vhi;
    __nv_bfloat16* dl = (slot < 16) ? qlo : (slot < 32) ? klo : vlo;
    ((uint32_t*)dh)[d] = *(uint32_t*)&hp;
    ((uint32_t*)dl)[d] = pkf(l0, l1);
}

// ---------------------------------------------------------------------------
// Tensor-core flash attention (causal, scale=8). BM=64 (4 warps x m16),
// BN=64, DH=64, cp.async double-buffered K/V hi/lo, bf16-split everywhere.
// ---------------------------------------------------------------------------
#define VSTR 72
#define MATB (64 * VSTR * 2)          // bytes per matrix
#define FSTGB (4 * MATB)              // bytes per stage
#define FSMEM2 (2 * FSTGB)

__global__ __launch_bounds__(128) void flash_tc(
    const __nv_bfloat16* __restrict__ qhi, const __nv_bfloat16* __restrict__ qlo,
    const __nv_bfloat16* __restrict__ khi, const __nv_bfloat16* __restrict__ klo,
    const __nv_bfloat16* __restrict__ vhi, const __nv_bfloat16* __restrict__ vlo,
    __nv_bfloat16* __restrict__ ohi, __nv_bfloat16* __restrict__ olo)
{
    extern __shared__ __align__(16) __nv_bfloat16 smx[];
    const uint32_t sb = smem_u32(smx);
    const int qb = blockIdx.x, head = blockIdx.y;
    const int t = threadIdx.x, w = t >> 5, lane = t & 31;
    const int hcol = head * DH;

    const int lr = t >> 1, lh = (t & 1) * 32;

    auto ldstage = [&](uint32_t base, const __nv_bfloat16* mhi,
                       const __nv_bfloat16* mlo, int seq0) {
        const size_t g = (size_t)(seq0 + lr) * D_MODEL + hcol + lh;
        uint32_t d = base + (uint32_t)((lr * VSTR + lh) * 2);
        #pragma unroll
        for (int q2 = 0; q2 < 4; q2++) {
            cp16(d + q2 * 16,        mhi + g + q2 * 8);
            cp16(d + MATB + q2 * 16, mlo + g + q2 * 8);
        }
    };

    // ---- stage Q through stage-0 K slots, load A-fragments
    ldstage(sb, qhi, qlo, qb * 64);
    asm volatile("cp.async.commit_group;");
    asm volatile("cp.async.wait_group 0;");
    __syncthreads();

    const int a_row = (lane & 7) + (lane & 8);
    const int a_col = (lane >> 4) << 3;
    uint32_t ah[4][4], al[4][4];
    #pragma unroll
    for (int kc = 0; kc < 4; kc++) {
        uint32_t off = (uint32_t)(((w * 16 + a_row) * VSTR + kc * 16 + a_col) * 2);
        ldm4(ah[kc], sb + off);
        ldm4(al[kc], sb + MATB + off);
    }
    __syncthreads();

    auto issue = [&](int stage, int jb) {
        uint32_t s0 = sb + (uint32_t)(stage * FSTGB);
        ldstage(s0,            khi, klo, jb * 64);
        ldstage(s0 + 2 * MATB, vhi, vlo, jb * 64);
        asm volatile("cp.async.commit_group;");
    };
    issue(0, 0);
    if (qb >= 1) issue(1, 1);

    float o[8][4];
    #pragma unroll
    for (int i = 0; i < 8; i++)
        #pragma unroll
        for (int j = 0; j < 4; j++) o[i][j] = 0.f;
    float m0 = -1e30f, m1 = -1e30f, l0 = 0.f, l1 = 0.f;

    const int b_row = (lane & 7) + ((lane & 16) >> 1);
    const int b_col = lane & 8;
    const int vg = lane >> 3;
    const int v_row = (vg & 1) * 8 + (lane & 7);
    const int v_col = (vg >> 1) * 8;
    const int myrow0 = qb * 64 + w * 16 + (lane >> 2);

    for (int jb = 0; jb <= qb; jb++) {
        if (jb < qb) asm volatile("cp.async.wait_group 1;");
        else         asm volatile("cp.async.wait_group 0;");
        __syncthreads();

        const uint32_t s0 = sb + (uint32_t)((jb & 1) * FSTGB);
        const uint32_t pKh = s0, pKl = s0 + MATB;
        const uint32_t pVh = s0 + 2 * MATB, pVl = s0 + 3 * MATB;

        float s[8][4];
        #pragma unroll
        for (int i = 0; i < 8; i++)
            #pragma unroll
            for (int j = 0; j < 4; j++) s[i][j] = 0.f;

        #pragma unroll
        for (int kc = 0; kc < 4; kc++) {
            uint32_t bh[4][4], bl[4][4];
            #pragma unroll
            for (int p = 0; p < 4; p++) {
                uint32_t off = (uint32_t)(((p * 16 + b_row) * VSTR + kc * 16 + b_col) * 2);
                ldm4(bh[p], pKh + off);
                ldm4(bl[p], pKl + off);
            }
            #pragma unroll
            for (int nt = 0; nt < 8; nt++) {
                int p = nt >> 1, si = (nt & 1) * 2;
                mma16816(s[nt], ah[kc], bh[p][si], bh[p][si + 1]);
                mma16816(s[nt], ah[kc], bl[p][si], bl[p][si + 1]);
                mma16816(s[nt], al[kc], bh[p][si], bh[p][si + 1]);
            }
        }

        if (jb == qb) {
            #pragma unroll
            for (int nt = 0; nt < 8; nt++) {
                int colb = jb * 64 + nt * 8 + (lane & 3) * 2;
                #pragma unroll
                for (int c = 0; c < 4; c++) {
                    int col = colb + (c & 1);
                    int row = myrow0 + (c >> 1) * 8;
                    s[nt][c] = (col > row) ? -1e30f : s[nt][c] * 8.0f;
                }
            }
        } else {
            #pragma unroll
            for (int nt = 0; nt < 8; nt++)
                #pragma unroll
                for (int c = 0; c < 4; c++) s[nt][c] *= 8.0f;
        }

        float mx0 = -1e30f, mx1 = -1e30f;
        #pragma unroll
        for (int nt = 0; nt < 8; nt++) {
            mx0 = fmaxf(mx0, fmaxf(s[nt][0], s[nt][1]));
            mx1 = fmaxf(mx1, fmaxf(s[nt][2], s[nt][3]));
        }
        mx0 = fmaxf(mx0, __shfl_xor_sync(0xffffffffu, mx0, 1));
        mx0 = fmaxf(mx0, __shfl_xor_sync(0xffffffffu, mx0, 2));
        mx1 = fmaxf(mx1, __shfl_xor_sync(0xffffffffu, mx1, 1));
        mx1 = fmaxf(mx1, __shfl_xor_sync(0xffffffffu, mx1, 2));
        float mn0 = fmaxf(m0, mx0), mn1 = fmaxf(m1, mx1);
        float c0 = __expf(m0 - mn0), c1 = __expf(m1 - mn1);
        m0 = mn0; m1 = mn1;

        float rs0 = 0.f, rs1 = 0.f;
        #pragma unroll
        for (int nt = 0; nt < 8; nt++) {
            s[nt][0] = __expf(s[nt][0] - mn0);
            s[nt][1] = __expf(s[nt][1] - mn0);
            s[nt][2] = __expf(s[nt][2] - mn1);
            s[nt][3] = __expf(s[nt][3] - mn1);
            rs0 += s[nt][0] + s[nt][1];
            rs1 += s[nt][2] + s[nt][3];
        }
        rs0 += __shfl_xor_sync(0xffffffffu, rs0, 1);
        rs0 += __shfl_xor_sync(0xffffffffu, rs0, 2);
        rs1 += __shfl_xor_sync(0xffffffffu, rs1, 1);
        rs1 += __shfl_xor_sync(0xffffffffu, rs1, 2);
        l0 = l0 * c0 + rs0;
        l1 = l1 * c1 + rs1;
        #pragma unroll
        for (int nt = 0; nt < 8; nt++) {
            o[nt][0] *= c0; o[nt][1] *= c0;
            o[nt][2] *= c1; o[nt][3] *= c1;
        }

        #pragma unroll
        for (int kt = 0; kt < 4; kt++) {
            uint32_t pa_h[4], pa_l[4];
            #pragma unroll
            for (int hh = 0; hh < 2; hh++) {
                const float* sv = s[2 * kt + hh];
                __nv_bfloat16 h0 = __float2bfloat16(sv[0]);
                __nv_bfloat16 h1 = __float2bfloat16(sv[1]);
                __nv_bfloat16 h2 = __float2bfloat16(sv[2]);
                __nv_bfloat16 h3 = __float2bfloat16(sv[3]);
                __nv_bfloat162 p01 = __halves2bfloat162(h0, h1);
                __nv_bfloat162 p23 = __halves2bfloat162(h2, h3);
                pa_h[2 * hh]     = *(uint32_t*)&p01;
                pa_h[2 * hh + 1] = *(uint32_t*)&p23;
                pa_l[2 * hh]     = pkf(sv[0] - __bfloat162float(h0),
                                       sv[1] - __bfloat162float(h1));
                pa_l[2 * hh + 1] = pkf(sv[2] - __bfloat162float(h2),
                                       sv[3] - __bfloat162float(h3));
            }
            uint32_t afh[4] = {pa_h[0], pa_h[1], pa_h[2], pa_h[3]};
            uint32_t afl[4] = {pa_l[0], pa_l[1], pa_l[2], pa_l[3]};

            #pragma unroll
            for (int nc = 0; nc < 4; nc++) {
                uint32_t off = (uint32_t)(((kt * 16 + v_row) * VSTR + nc * 16 + v_col) * 2);
                uint32_t vbh[4], vbl[4];
                ldm4t(vbh, pVh + off);
                ldm4t(vbl, pVl + off);
                mma16816(o[2 * nc],     afh, vbh[0], vbh[1]);
                mma16816(o[2 * nc],     afh, vbl[0], vbl[1]);
                mma16816(o[2 * nc],     afl, vbh[0], vbh[1]);
                mma16816(o[2 * nc + 1], afh, vbh[2], vbh[3]);
                mma16816(o[2 * nc + 1], afh, vbl[2], vbl[3]);
                mma16816(o[2 * nc + 1], afl, vbh[2], vbh[3]);
            }
        }

        __syncthreads();
        if (jb + 2 <= qb) issue(jb & 1, jb + 2);
    }

    float inv0 = 1.0f / l0, inv1 = 1.0f / l1;
    #pragma unroll
    for (int nt = 0; nt < 8; nt++) {
        int col = hcol + nt * 8 + (lane & 3) * 2;
        {
            float x = o[nt][0] * inv0, y = o[nt][1] * inv0;
            __nv_bfloat16 hx = __float2bfloat16(x), hy = __float2bfloat16(y);
            __nv_bfloat162 hp = __halves2bfloat162(hx, hy);
            size_t d = ((size_t)myrow0 * D_MODEL + col) / 2;
            ((uint32_t*)ohi)[d] = *(uint32_t*)&hp;
            ((uint32_t*)olo)[d] = pkf(x - __bfloat162float(hx), y - __bfloat162float(hy));
        }
        {
            float x = o[nt][2] * inv1, y = o[nt][3] * inv1;
            __nv_bfloat16 hx = __float2bfloat16(x), hy = __float2bfloat16(y);
            __nv_bfloat162 hp = __halves2bfloat162(hx, hy);
            size_t d = ((size_t)(myrow0 + 8) * D_MODEL + col) / 2;
            ((uint32_t*)ohi)[d] = *(uint32_t*)&hp;
            ((uint32_t*)olo)[d] = pkf(x - __bfloat162float(hx), y - __bfloat162float(hy));
        }
    }
}

// ---------------------------------------------------------------------------
extern "C" void kernel_launch(void* const* d_in, const int* in_sizes, int n_in,
                              void* d_out, int out_size)
{
    const float* x  = (const float*)d_in[0];
    const float* Wq = (const float*)d_in[1];
    const float* Wk = (const float*)d_in[2];
    const float* Wv = (const float*)d_in[3];
    const float* Wo = (const float*)d_in[4];

    float* qkv;
    __nv_bfloat16 *xhi, *xlo, *qhi, *qlo, *khi, *klo, *vhi, *vlo, *ohi, *olo, *wh, *wl;
    cudaGetSymbolAddress((void**)&qkv, g_qkv);
    cudaGetSymbolAddress((void**)&xhi, g_xhi);
    cudaGetSymbolAddress((void**)&xlo, g_xlo);
    cudaGetSymbolAddress((void**)&qhi, g_qhi);
    cudaGetSymbolAddress((void**)&qlo, g_qlo);
    cudaGetSymbolAddress((void**)&khi, g_khi);
    cudaGetSymbolAddress((void**)&klo, g_klo);
    cudaGetSymbolAddress((void**)&vhi, g_vhi);
    cudaGetSymbolAddress((void**)&vlo, g_vlo);
    cudaGetSymbolAddress((void**)&ohi, g_ohi);
    cudaGetSymbolAddress((void**)&olo, g_olo);
    cudaGetSymbolAddress((void**)&wh, g_wh);
    cudaGetSymbolAddress((void**)&wl, g_wl);

    cudaFuncSetAttribute(gemm_tc2,
                         cudaFuncAttributeMaxDynamicSharedMemorySize, GSMEM3);
    cudaFuncSetAttribute(flash_tc,
                         cudaFuncAttributeMaxDynamicSharedMemorySize, FSMEM2);

    const int NE4 = NSEQ * D_MODEL / 4;
    dim3 tgrid(D_MODEL / 32, D_MODEL / 32);
    dim3 tblk(32, 8);

    split_kernel<<<NE4 / 256, 256>>>(x, xhi, xlo);
    tconv_kernel<<<tgrid, tblk>>>(Wq, wh, wl, 0);
    tconv_kernel<<<tgrid, tblk>>>(Wk, wh, wl, 1024);
    tconv_kernel<<<tgrid, tblk>>>(Wv, wh, wl, 2048);

    gemm_tc2<<<dim3(D3 / 128, NSEQ / 128), 256, GSMEM3>>>(
        xhi, xlo, wh, wl, qkv, NSEQ, D3, D_MODEL);

    l2split_kernel<<<NSEQ * 48 / 8, 256>>>(qkv, qhi, qlo, khi, klo, vhi, vlo);

    flash_tc<<<dim3(NSEQ / 64, HEADS), 128, FSMEM2>>>(
        qhi, qlo, khi, klo, vhi, vlo, ohi, olo);

    tconv_kernel<<<tgrid, tblk>>>(Wo, wh, wl, 0);
    gemm_tc2<<<dim3(D_MODEL / 128, NSEQ / 128), 256, GSMEM3>>>(
        ohi, olo, wh, wl, (float*)d_out, NSEQ, D_MODEL, D_MODEL);
}

// round 10
// speedup vs baseline: 2.6906x; 1.0092x over previous
#include <cuda_runtime.h>
#include <cuda_bf16.h>
#include <math.h>
#include <stdint.h>

#define D_MODEL 1024
#define D3      3072
#define NSEQ    4096
#define HEADS   16
#define DH      64

// Scratch (allocation-free rule: __device__ globals)
__device__ float g_qkv[NSEQ * D3];                  // fused q|k|v, stride 3072
__device__ __nv_bfloat16 g_xhi[NSEQ * D_MODEL];
__device__ __nv_bfloat16 g_xlo[NSEQ * D_MODEL];
__device__ __nv_bfloat16 g_qhi[NSEQ * D_MODEL];
__device__ __nv_bfloat16 g_qlo[NSEQ * D_MODEL];
__device__ __nv_bfloat16 g_khi[NSEQ * D_MODEL];
__device__ __nv_bfloat16 g_klo[NSEQ * D_MODEL];
__device__ __nv_bfloat16 g_vhi[NSEQ * D_MODEL];
__device__ __nv_bfloat16 g_vlo[NSEQ * D_MODEL];
__device__ __nv_bfloat16 g_ohi[NSEQ * D_MODEL];
__device__ __nv_bfloat16 g_olo[NSEQ * D_MODEL];
__device__ __nv_bfloat16 g_wh[D3 * D_MODEL];        // W^T hi  [N][K] (concat)
__device__ __nv_bfloat16 g_wl[D3 * D_MODEL];        // W^T lo  [N][K]

__device__ __forceinline__ uint32_t smem_u32(const void* p) {
    uint32_t a;
    asm("{ .reg .u64 t; cvta.to.shared.u64 t, %1; cvt.u32.u64 %0, t; }"
        : "=r"(a) : "l"(p));
    return a;
}

__device__ __forceinline__ void ldm4(uint32_t r[4], uint32_t addr) {
    asm volatile("ldmatrix.sync.aligned.m8n8.x4.shared.b16 {%0,%1,%2,%3}, [%4];"
                 : "=r"(r[0]), "=r"(r[1]), "=r"(r[2]), "=r"(r[3]) : "r"(addr));
}

__device__ __forceinline__ void ldm4t(uint32_t r[4], uint32_t addr) {
    asm volatile("ldmatrix.sync.aligned.m8n8.x4.trans.shared.b16 {%0,%1,%2,%3}, [%4];"
                 : "=r"(r[0]), "=r"(r[1]), "=r"(r[2]), "=r"(r[3]) : "r"(addr));
}

__device__ __forceinline__ void mma16816(float d[4], const uint32_t a[4],
                                         uint32_t b0, uint32_t b1) {
    asm volatile(
        "mma.sync.aligned.m16n8k16.row.col.f32.bf16.bf16.f32 "
        "{%0,%1,%2,%3}, {%4,%5,%6,%7}, {%8,%9}, {%0,%1,%2,%3};"
        : "+f"(d[0]), "+f"(d[1]), "+f"(d[2]), "+f"(d[3])
        : "r"(a[0]), "r"(a[1]), "r"(a[2]), "r"(a[3]), "r"(b0), "r"(b1));
}

__device__ __forceinline__ void cp16(uint32_t dst, const void* src) {
    asm volatile("cp.async.cg.shared.global [%0], [%1], 16;"
                 :: "r"(dst), "l"(src));
}

__device__ __forceinline__ uint32_t pkf(float x, float y) {
    __nv_bfloat162 h = __floats2bfloat162_rn(x, y);
    return *(uint32_t*)&h;
}

// ---------------------------------------------------------------------------
// split: fp32 -> (hi, lo) bf16, same layout. 4 elements / thread.
// ---------------------------------------------------------------------------
__global__ void split_kernel(const float* __restrict__ in,
                             __nv_bfloat16* __restrict__ hi,
                             __nv_bfloat16* __restrict__ lo)
{
    int i = blockIdx.x * blockDim.x + threadIdx.x;
    float4 v = ((const float4*)in)[i];
    __nv_bfloat16 h0 = __float2bfloat16(v.x), h1 = __float2bfloat16(v.y);
    __nv_bfloat16 h2 = __float2bfloat16(v.z), h3 = __float2bfloat16(v.w);
    float l0 = v.x - __bfloat162float(h0), l1 = v.y - __bfloat162float(h1);
    float l2 = v.z - __bfloat162float(h2), l3 = v.w - __bfloat162float(h3);
    __nv_bfloat162 hA = __halves2bfloat162(h0, h1), hB = __halves2bfloat162(h2, h3);
    ((uint2*)hi)[i] = make_uint2(*(uint32_t*)&hA, *(uint32_t*)&hB);
    ((uint2*)lo)[i] = make_uint2(pkf(l0, l1), pkf(l2, l3));
}

// ---------------------------------------------------------------------------
// transpose-convert: W[k][n] fp32 -> W^T hi/lo bf16 at rows [rowoff, +1024)
// ---------------------------------------------------------------------------
__global__ void tconv_kernel(const float* __restrict__ W,
                             __nv_bfloat16* __restrict__ hiT,
                             __nv_bfloat16* __restrict__ loT, int rowoff)
{
    __shared__ float tile[32][33];
    const int n0 = blockIdx.x * 32, k0 = blockIdx.y * 32;
    const int tx = threadIdx.x, ty = threadIdx.y;   // 32 x 8
    #pragma unroll
    for (int j = 0; j < 4; j++)
        tile[ty + 8 * j][tx] = W[(size_t)(k0 + ty + 8 * j) * D_MODEL + n0 + tx];
    __syncthreads();
    #pragma unroll
    for (int j = 0; j < 4; j++) {
        float v = tile[tx][ty + 8 * j];
        __nv_bfloat16 h = __float2bfloat16(v);
        __nv_bfloat16 l = __float2bfloat16(v - __bfloat162float(h));
        size_t o = (size_t)(rowoff + n0 + ty + 8 * j) * D_MODEL + k0 + tx;
        hiT[o] = h;
        loT[o] = l;
    }
}

// ---------------------------------------------------------------------------
// Pipelined split-bf16 GEMM.  C[M,N] = A[M,K] @ B[K,N].  CTA 128x256, BK=32,
// 8 warps (2x4), warp tile 64x64, 3-stage cp.async, one barrier/iter.
// ---------------------------------------------------------------------------
#define ASTR 40
#define A_SZ (128 * ASTR * 2)                 // bytes per A matrix per stage
#define B_SZ (256 * ASTR * 2)                 // bytes per B matrix per stage
#define STG_BYTES (2 * A_SZ + 2 * B_SZ)       // 61440
#define GSMEM3 (3 * STG_BYTES)                // 184320

__global__ __launch_bounds__(256, 1) void gemm_tc3(
    const __nv_bfloat16* __restrict__ Ahi, const __nv_bfloat16* __restrict__ Alo,
    const __nv_bfloat16* __restrict__ BhiT, const __nv_bfloat16* __restrict__ BloT,
    float* __restrict__ C, int M, int N, int K)
{
    extern __shared__ __align__(16) __nv_bfloat16 smg[];
    const uint32_t sb = smem_u32(smg);
    const int t = threadIdx.x;
    const int wid = t >> 5, lane = t & 31;
    const int row0 = blockIdx.y * 128, col0 = blockIdx.x * 256;
    const int wm = (wid >> 2) * 64;    // 0 / 64
    const int wn = (wid & 3) * 64;     // 0..192

    const int r_c = t >> 2, c_c = t & 3;   // cp.async coords

    float acc[4][8][4];
    #pragma unroll
    for (int i = 0; i < 4; i++)
        #pragma unroll
        for (int j = 0; j < 8; j++)
            #pragma unroll
            for (int q = 0; q < 4; q++) acc[i][j][q] = 0.f;

    auto issue = [&](int stage, int k0) {
        uint32_t s0 = sb + (uint32_t)(stage * STG_BYTES);
        // A: rows r_c, r_c+64 (hi & lo)
        #pragma unroll
        for (int h = 0; h < 2; h++) {
            int r = r_c + h * 64;
            uint32_t o = (uint32_t)((r * ASTR + c_c * 8) * 2);
            const size_t g = (size_t)(row0 + r) * K + k0 + c_c * 8;
            cp16(s0 + o,        Ahi + g);
            cp16(s0 + A_SZ + o, Alo + g);
        }
        // B: rows r_c, +64, +128, +192 (hi & lo)
        #pragma unroll
        for (int h = 0; h < 4; h++) {
            int r = r_c + h * 64;
            uint32_t o = (uint32_t)((r * ASTR + c_c * 8) * 2);
            const size_t g = (size_t)(col0 + r) * K + k0 + c_c * 8;
            cp16(s0 + 2 * A_SZ + o,        BhiT + g);
            cp16(s0 + 2 * A_SZ + B_SZ + o, BloT + g);
        }
        asm volatile("cp.async.commit_group;");
    };

    issue(0, 0);
    issue(1, 32);

    const int a_row = (lane & 7) + (lane & 8);
    const int a_col = (lane >> 4) << 3;
    const int b_row = (lane & 7) + ((lane & 16) >> 1);
    const int b_col = lane & 8;

    const int NIT = K >> 5;          // 32
    int stage = 0;
    for (int it = 0; it < NIT; it++) {
        asm volatile("cp.async.wait_group 1;");
        __syncthreads();

        const uint32_t s0 = sb + (uint32_t)(stage * STG_BYTES);
        const uint32_t sAh = s0;
        const uint32_t sAl = s0 + A_SZ;
        const uint32_t sBh = s0 + 2 * A_SZ;
        const uint32_t sBl = s0 + 2 * A_SZ + B_SZ;

        #pragma unroll
        for (int ks = 0; ks < 2; ks++) {
            const int kb = ks * 16;
            uint32_t ah[4][4], al[4][4];
            #pragma unroll
            for (int mt = 0; mt < 4; mt++) {
                uint32_t off = (uint32_t)(((wm + mt * 16 + a_row) * ASTR + kb + a_col) * 2);
                ldm4(ah[mt], sAh + off);
                ldm4(al[mt], sAl + off);
            }
            #pragma unroll
            for (int p = 0; p < 4; p++) {
                uint32_t bh[4], bl[4];
                uint32_t off = (uint32_t)(((wn + p * 16 + b_row) * ASTR + kb + b_col) * 2);
                ldm4(bh, sBh + off);
                ldm4(bl, sBl + off);
                #pragma unroll
                for (int mt = 0; mt < 4; mt++) {
                    #pragma unroll
                    for (int half = 0; half < 2; half++) {
                        int nt = p * 2 + half, si = half * 2;
                        mma16816(acc[mt][nt], ah[mt], bh[si], bh[si + 1]);
                        mma16816(acc[mt][nt], ah[mt], bl[si], bl[si + 1]);
                        mma16816(acc[mt][nt], al[mt], bh[si], bh[si + 1]);
                    }
                }
            }
        }

        if (it + 2 < NIT) {
            int ns = stage + 2;
            if (ns >= 3) ns -= 3;
            issue(ns, (it + 2) * 32);
        }
        stage = (stage + 1 == 3) ? 0 : stage + 1;
    }

    #pragma unroll
    for (int mt = 0; mt < 4; mt++)
        #pragma unroll
        for (int nt = 0; nt < 8; nt++) {
            int row = row0 + wm + mt * 16 + (lane >> 2);
            int col = col0 + wn + nt * 8 + (lane & 3) * 2;
            *(float2*)(C + (size_t)row * N + col) =
                make_float2(acc[mt][nt][0], acc[mt][nt][1]);
            *(float2*)(C + (size_t)(row + 8) * N + col) =
                make_float2(acc[mt][nt][2], acc[mt][nt][3]);
        }
}

// ---------------------------------------------------------------------------
// l2norm (q,k) + bf16 hi/lo split of q,k,v from the fused qkv buffer.
// ---------------------------------------------------------------------------
__global__ void l2split_kernel(const float* __restrict__ qkv,
                               __nv_bfloat16* __restrict__ qhi, __nv_bfloat16* __restrict__ qlo,
                               __nv_bfloat16* __restrict__ khi, __nv_bfloat16* __restrict__ klo,
                               __nv_bfloat16* __restrict__ vhi, __nv_bfloat16* __restrict__ vlo)
{
    int w    = (blockIdx.x * blockDim.x + threadIdx.x) >> 5;
    int lane = threadIdx.x & 31;
    int n    = w / 48;
    int slot = w % 48;
    const float* p = qkv + (size_t)n * D3 + slot * 64;
    float2 vv = ((const float2*)p)[lane];

    if (slot < 32) {
        float ss = vv.x * vv.x + vv.y * vv.y;
        #pragma unroll
        for (int off = 16; off; off >>= 1)
            ss += __shfl_xor_sync(0xffffffffu, ss, off);
        float s = 1.0f / fmaxf(sqrtf(ss), 1e-12f);
        vv.x *= s;
        vv.y *= s;
    }
    __nv_bfloat16 h0 = __float2bfloat16(vv.x), h1 = __float2bfloat16(vv.y);
    float l0 = vv.x - __bfloat162float(h0), l1 = vv.y - __bfloat162float(h1);
    __nv_bfloat162 hp = __halves2bfloat162(h0, h1);

    size_t d = ((size_t)n * D_MODEL + (slot & 15) * 64 + lane * 2) / 2;
    __nv_bfloat16* dh = (slot < 16) ? qhi : (slot < 32) ? khi : vhi;
    __nv_bfloat16* dl = (slot < 16) ? qlo : (slot < 32) ? klo : vlo;
    ((uint32_t*)dh)[d] = *(uint32_t*)&hp;
    ((uint32_t*)dl)[d] = pkf(l0, l1);
}

// ---------------------------------------------------------------------------
// Tensor-core flash attention (causal, scale=8). BM=64 (4 warps x m16),
// BN=64, DH=64, cp.async double-buffered K/V hi/lo, bf16-split everywhere.
// ---------------------------------------------------------------------------
#define VSTR 72
#define MATB (64 * VSTR * 2)          // bytes per matrix
#define FSTGB (4 * MATB)              // bytes per stage
#define FSMEM2 (2 * FSTGB)

__global__ __launch_bounds__(128) void flash_tc(
    const __nv_bfloat16* __restrict__ qhi, const __nv_bfloat16* __restrict__ qlo,
    const __nv_bfloat16* __restrict__ khi, const __nv_bfloat16* __restrict__ klo,
    const __nv_bfloat16* __restrict__ vhi, const __nv_bfloat16* __restrict__ vlo,
    __nv_bfloat16* __restrict__ ohi, __nv_bfloat16* __restrict__ olo)
{
    extern __shared__ __align__(16) __nv_bfloat16 smx[];
    const uint32_t sb = smem_u32(smx);
    const int qb = blockIdx.x, head = blockIdx.y;
    const int t = threadIdx.x, w = t >> 5, lane = t & 31;
    const int hcol = head * DH;

    const int lr = t >> 1, lh = (t & 1) * 32;

    auto ldstage = [&](uint32_t base, const __nv_bfloat16* mhi,
                       const __nv_bfloat16* mlo, int seq0) {
        const size_t g = (size_t)(seq0 + lr) * D_MODEL + hcol + lh;
        uint32_t d = base + (uint32_t)((lr * VSTR + lh) * 2);
        #pragma unroll
        for (int q2 = 0; q2 < 4; q2++) {
            cp16(d + q2 * 16,        mhi + g + q2 * 8);
            cp16(d + MATB + q2 * 16, mlo + g + q2 * 8);
        }
    };

    // ---- stage Q through stage-0 K slots, load A-fragments
    ldstage(sb, qhi, qlo, qb * 64);
    asm volatile("cp.async.commit_group;");
    asm volatile("cp.async.wait_group 0;");
    __syncthreads();

    const int a_row = (lane & 7) + (lane & 8);
    const int a_col = (lane >> 4) << 3;
    uint32_t ah[4][4], al[4][4];
    #pragma unroll
    for (int kc = 0; kc < 4; kc++) {
        uint32_t off = (uint32_t)(((w * 16 + a_row) * VSTR + kc * 16 + a_col) * 2);
        ldm4(ah[kc], sb + off);
        ldm4(al[kc], sb + MATB + off);
    }
    __syncthreads();

    auto issue = [&](int stage, int jb) {
        uint32_t s0 = sb + (uint32_t)(stage * FSTGB);
        ldstage(s0,            khi, klo, jb * 64);
        ldstage(s0 + 2 * MATB, vhi, vlo, jb * 64);
        asm volatile("cp.async.commit_group;");
    };
    issue(0, 0);
    if (qb >= 1) issue(1, 1);

    float o[8][4];
    #pragma unroll
    for (int i = 0; i < 8; i++)
        #pragma unroll
        for (int j = 0; j < 4; j++) o[i][j] = 0.f;
    float m0 = -1e30f, m1 = -1e30f, l0 = 0.f, l1 = 0.f;

    const int b_row = (lane & 7) + ((lane & 16) >> 1);
    const int b_col = lane & 8;
    const int vg = lane >> 3;
    const int v_row = (vg & 1) * 8 + (lane & 7);
    const int v_col = (vg >> 1) * 8;
    const int myrow0 = qb * 64 + w * 16 + (lane >> 2);

    for (int jb = 0; jb <= qb; jb++) {
        if (jb < qb) asm volatile("cp.async.wait_group 1;");
        else         asm volatile("cp.async.wait_group 0;");
        __syncthreads();

        const uint32_t s0 = sb + (uint32_t)((jb & 1) * FSTGB);
        const uint32_t pKh = s0, pKl = s0 + MATB;
        const uint32_t pVh = s0 + 2 * MATB, pVl = s0 + 3 * MATB;

        float s[8][4];
        #pragma unroll
        for (int i = 0; i < 8; i++)
            #pragma unroll
            for (int j = 0; j < 4; j++) s[i][j] = 0.f;

        #pragma unroll
        for (int kc = 0; kc < 4; kc++) {
            uint32_t bh[4][4], bl[4][4];
            #pragma unroll
            for (int p = 0; p < 4; p++) {
                uint32_t off = (uint32_t)(((p * 16 + b_row) * VSTR + kc * 16 + b_col) * 2);
                ldm4(bh[p], pKh + off);
                ldm4(bl[p], pKl + off);
            }
            #pragma unroll
            for (int nt = 0; nt < 8; nt++) {
                int p = nt >> 1, si = (nt & 1) * 2;
                mma16816(s[nt], ah[kc], bh[p][si], bh[p][si + 1]);
                mma16816(s[nt], ah[kc], bl[p][si], bl[p][si + 1]);
                mma16816(s[nt], al[kc], bh[p][si], bh[p][si + 1]);
            }
        }

        if (jb == qb) {
            #pragma unroll
            for (int nt = 0; nt < 8; nt++) {
                int colb = jb * 64 + nt * 8 + (lane & 3) * 2;
                #pragma unroll
                for (int c = 0; c < 4; c++) {
                    int col = colb + (c & 1);
                    int row = myrow0 + (c >> 1) * 8;
                    s[nt][c] = (col > row) ? -1e30f : s[nt][c] * 8.0f;
                }
            }
        } else {
            #pragma unroll
            for (int nt = 0; nt < 8; nt++)
                #pragma unroll
                for (int c = 0; c < 4; c++) s[nt][c] *= 8.0f;
        }

        float mx0 = -1e30f, mx1 = -1e30f;
        #pragma unroll
        for (int nt = 0; nt < 8; nt++) {
            mx0 = fmaxf(mx0, fmaxf(s[nt][0], s[nt][1]));
            mx1 = fmaxf(mx1, fmaxf(s[nt][2], s[nt][3]));
        }
        mx0 = fmaxf(mx0, __shfl_xor_sync(0xffffffffu, mx0, 1));
        mx0 = fmaxf(mx0, __shfl_xor_sync(0xffffffffu, mx0, 2));
        mx1 = fmaxf(mx1, __shfl_xor_sync(0xffffffffu, mx1, 1));
        mx1 = fmaxf(mx1, __shfl_xor_sync(0xffffffffu, mx1, 2));
        float mn0 = fmaxf(m0, mx0), mn1 = fmaxf(m1, mx1);
        float c0 = __expf(m0 - mn0), c1 = __expf(m1 - mn1);
        m0 = mn0; m1 = mn1;

        float rs0 = 0.f, rs1 = 0.f;
        #pragma unroll
        for (int nt = 0; nt < 8; nt++) {
            s[nt][0] = __expf(s[nt][0] - mn0);
            s[nt][1] = __expf(s[nt][1] - mn0);
            s[nt][2] = __expf(s[nt][2] - mn1);
            s[nt][3] = __expf(s[nt][3] - mn1);
            rs0 += s[nt][0] + s[nt][1];
            rs1 += s[nt][2] + s[nt][3];
        }
        rs0 += __shfl_xor_sync(0xffffffffu, rs0, 1);
        rs0 += __shfl_xor_sync(0xffffffffu, rs0, 2);
        rs1 += __shfl_xor_sync(0xffffffffu, rs1, 1);
        rs1 += __shfl_xor_sync(0xffffffffu, rs1, 2);
        l0 = l0 * c0 + rs0;
        l1 = l1 * c1 + rs1;
        #pragma unroll
        for (int nt = 0; nt < 8; nt++) {
            o[nt][0] *= c0; o[nt][1] *= c0;
            o[nt][2] *= c1; o[nt][3] *= c1;
        }

        #pragma unroll
        for (int kt = 0; kt < 4; kt++) {
            uint32_t pa_h[4], pa_l[4];
            #pragma unroll
            for (int hh = 0; hh < 2; hh++) {
                const float* sv = s[2 * kt + hh];
                __nv_bfloat16 h0 = __float2bfloat16(sv[0]);
                __nv_bfloat16 h1 = __float2bfloat16(sv[1]);
                __nv_bfloat16 h2 = __float2bfloat16(sv[2]);
                __nv_bfloat16 h3 = __float2bfloat16(sv[3]);
                __nv_bfloat162 p01 = __halves2bfloat162(h0, h1);
                __nv_bfloat162 p23 = __halves2bfloat162(h2, h3);
                pa_h[2 * hh]     = *(uint32_t*)&p01;
                pa_h[2 * hh + 1] = *(uint32_t*)&p23;
                pa_l[2 * hh]     = pkf(sv[0] - __bfloat162float(h0),
                                       sv[1] - __bfloat162float(h1));
                pa_l[2 * hh + 1] = pkf(sv[2] - __bfloat162float(h2),
                                       sv[3] - __bfloat162float(h3));
            }
            uint32_t afh[4] = {pa_h[0], pa_h[1], pa_h[2], pa_h[3]};
            uint32_t afl[4] = {pa_l[0], pa_l[1], pa_l[2], pa_l[3]};

            #pragma unroll
            for (int nc = 0; nc < 4; nc++) {
                uint32_t off = (uint32_t)(((kt * 16 + v_row) * VSTR + nc * 16 + v_col) * 2);
                uint32_t vbh[4], vbl[4];
                ldm4t(vbh, pVh + off);
                ldm4t(vbl, pVl + off);
                mma16816(o[2 * nc],     afh, vbh[0], vbh[1]);
                mma16816(o[2 * nc],     afh, vbl[0], vbl[1]);
                mma16816(o[2 * nc],     afl, vbh[0], vbh[1]);
                mma16816(o[2 * nc + 1], afh, vbh[2], vbh[3]);
                mma16816(o[2 * nc + 1], afh, vbl[2], vbl[3]);
                mma16816(o[2 * nc + 1], afl, vbh[2], vbh[3]);
            }
        }

        __syncthreads();
        if (jb + 2 <= qb) issue(jb & 1, jb + 2);
    }

    float inv0 = 1.0f / l0, inv1 = 1.0f / l1;
    #pragma unroll
    for (int nt = 0; nt < 8; nt++) {
        int col = hcol + nt * 8 + (lane & 3) * 2;
        {
            float x = o[nt][0] * inv0, y = o[nt][1] * inv0;
            __nv_bfloat16 hx = __float2bfloat16(x), hy = __float2bfloat16(y);
            __nv_bfloat162 hp = __halves2bfloat162(hx, hy);
            size_t d = ((size_t)myrow0 * D_MODEL + col) / 2;
            ((uint32_t*)ohi)[d] = *(uint32_t*)&hp;
            ((uint32_t*)olo)[d] = pkf(x - __bfloat162float(hx), y - __bfloat162float(hy));
        }
        {
            float x = o[nt][2] * inv1, y = o[nt][3] * inv1;
            __nv_bfloat16 hx = __float2bfloat16(x), hy = __float2bfloat16(y);
            __nv_bfloat162 hp = __halves2bfloat162(hx, hy);
            size_t d = ((size_t)(myrow0 + 8) * D_MODEL + col) / 2;
            ((uint32_t*)ohi)[d] = *(uint32_t*)&hp;
            ((uint32_t*)olo)[d] = pkf(x - __bfloat162float(hx), y - __bfloat162float(hy));
        }
    }
}

// ---------------------------------------------------------------------------
extern "C" void kernel_launch(void* const* d_in, const int* in_sizes, int n_in,
                              void* d_out, int out_size)
{
    const float* x  = (const float*)d_in[0];
    const float* Wq = (const float*)d_in[1];
    const float* Wk = (const float*)d_in[2];
    const float* Wv = (const float*)d_in[3];
    const float* Wo = (const float*)d_in[4];

    float* qkv;
    __nv_bfloat16 *xhi, *xlo, *qhi, *qlo, *khi, *klo, *vhi, *vlo, *ohi, *olo, *wh, *wl;
    cudaGetSymbolAddress((void**)&qkv, g_qkv);
    cudaGetSymbolAddress((void**)&xhi, g_xhi);
    cudaGetSymbolAddress((void**)&xlo, g_xlo);
    cudaGetSymbolAddress((void**)&qhi, g_qhi);
    cudaGetSymbolAddress((void**)&qlo, g_qlo);
    cudaGetSymbolAddress((void**)&khi, g_khi);
    cudaGetSymbolAddress((void**)&klo, g_klo);
    cudaGetSymbolAddress((void**)&vhi, g_vhi);
    cudaGetSymbolAddress((void**)&vlo, g_vlo);
    cudaGetSymbolAddress((void**)&ohi, g_ohi);
    cudaGetSymbolAddress((void**)&olo, g_olo);
    cudaGetSymbolAddress((void**)&wh, g_wh);
    cudaGetSymbolAddress((void**)&wl, g_wl);

    cudaFuncSetAttribute(gemm_tc3,
                         cudaFuncAttributeMaxDynamicSharedMemorySize, GSMEM3);
    cudaFuncSetAttribute(flash_tc,
                         cudaFuncAttributeMaxDynamicSharedMemorySize, FSMEM2);

    const int NE4 = NSEQ * D_MODEL / 4;
    dim3 tgrid(D_MODEL / 32, D_MODEL / 32);
    dim3 tblk(32, 8);

    split_kernel<<<NE4 / 256, 256>>>(x, xhi, xlo);
    tconv_kernel<<<tgrid, tblk>>>(Wq, wh, wl, 0);
    tconv_kernel<<<tgrid, tblk>>>(Wk, wh, wl, 1024);
    tconv_kernel<<<tgrid, tblk>>>(Wv, wh, wl, 2048);

    gemm_tc3<<<dim3(D3 / 256, NSEQ / 128), 256, GSMEM3>>>(
        xhi, xlo, wh, wl, qkv, NSEQ, D3, D_MODEL);

    l2split_kernel<<<NSEQ * 48 / 8, 256>>>(qkv, qhi, qlo, khi, klo, vhi, vlo);

    flash_tc<<<dim3(NSEQ / 64, HEADS), 128, FSMEM2>>>(
        qhi, qlo, khi, klo, vhi, vlo, ohi, olo);

    tconv_kernel<<<tgrid, tblk>>>(Wo, wh, wl, 0);
    gemm_tc3<<<dim3(D_MODEL / 256, NSEQ / 128), 256, GSMEM3>>>(
        ohi, olo, wh, wl, (float*)d_out, NSEQ, D_MODEL, D_MODEL);
}